// round 1
// baseline (speedup 1.0000x reference)
#include <cuda_runtime.h>
#include <math.h>

#define SEQ   4096
#define EMBED 4096
#define HEADS 16
#define HD    256
#define ROT   64

// ---------------- scratch (allocation-free rule: __device__ globals) ----------
__device__ float g_q [SEQ * EMBED];
__device__ float g_k [SEQ * EMBED];
__device__ float g_v [SEQ * EMBED];
__device__ float g_ao[SEQ * EMBED];

// ==============================================================================
// GEMM (NT): C[M,N] = A[M,K] * B[N,K]^T, M=N=K=4096, fp32
// 128x128 block tile, BK=16, 256 threads, 8x8 per thread (split 4+4 for
// conflict-free float4 smem reads).
// ==============================================================================
#define GBM 128
#define GBN 128
#define GBK 16

__global__ __launch_bounds__(256, 2)
void gemm_nt(const float* __restrict__ A, const float* __restrict__ B,
             float* __restrict__ C)
{
    __shared__ float As[GBK][GBM + 4];
    __shared__ float Bs[GBK][GBN + 4];

    const int tid = threadIdx.x;
    const int tx  = tid & 15;     // 0..15 -> N groups
    const int ty  = tid >> 4;     // 0..15 -> M groups
    const int m0  = blockIdx.y * GBM;
    const int n0  = blockIdx.x * GBN;

    float acc[8][8];
#pragma unroll
    for (int i = 0; i < 8; i++)
#pragma unroll
        for (int j = 0; j < 8; j++) acc[i][j] = 0.f;

    for (int kt = 0; kt < 4096; kt += GBK) {
        float4 a[2], b[2];
#pragma unroll
        for (int i = 0; i < 2; i++) {
            int f   = tid + 256 * i;
            int row = f >> 2;
            int c4  = f & 3;
            a[i] = *(const float4*)&A[(size_t)(m0 + row) * 4096 + kt + c4 * 4];
            b[i] = *(const float4*)&B[(size_t)(n0 + row) * 4096 + kt + c4 * 4];
        }
        __syncthreads();
#pragma unroll
        for (int i = 0; i < 2; i++) {
            int f   = tid + 256 * i;
            int row = f >> 2;
            int c4  = f & 3;
            As[c4 * 4 + 0][row] = a[i].x;
            As[c4 * 4 + 1][row] = a[i].y;
            As[c4 * 4 + 2][row] = a[i].z;
            As[c4 * 4 + 3][row] = a[i].w;
            Bs[c4 * 4 + 0][row] = b[i].x;
            Bs[c4 * 4 + 1][row] = b[i].y;
            Bs[c4 * 4 + 2][row] = b[i].z;
            Bs[c4 * 4 + 3][row] = b[i].w;
        }
        __syncthreads();
#pragma unroll
        for (int k = 0; k < GBK; k++) {
            float ra[8], rb[8];
            *(float4*)&ra[0] = *(float4*)&As[k][ty * 4];
            *(float4*)&ra[4] = *(float4*)&As[k][64 + ty * 4];
            *(float4*)&rb[0] = *(float4*)&Bs[k][tx * 4];
            *(float4*)&rb[4] = *(float4*)&Bs[k][64 + tx * 4];
#pragma unroll
            for (int i = 0; i < 8; i++)
#pragma unroll
                for (int j = 0; j < 8; j++)
                    acc[i][j] += ra[i] * rb[j];
        }
    }

#pragma unroll
    for (int i = 0; i < 8; i++) {
        int row = m0 + ((i < 4) ? (ty * 4 + i) : (64 + ty * 4 + (i - 4)));
        *(float4*)&C[(size_t)row * 4096 + n0 + tx * 4] =
            make_float4(acc[i][0], acc[i][1], acc[i][2], acc[i][3]);
        *(float4*)&C[(size_t)row * 4096 + n0 + 64 + tx * 4] =
            make_float4(acc[i][4], acc[i][5], acc[i][6], acc[i][7]);
    }
}

// ==============================================================================
// RoPE on first ROT=64 dims of each head, applied in place to Q and K.
// ==============================================================================
__global__ void rope_kernel(float* __restrict__ q, float* __restrict__ k)
{
    int idx = blockIdx.x * blockDim.x + threadIdx.x;   // SEQ*HEADS*32 threads
    int i = idx & 31;            // rotary pair index
    int h = (idx >> 5) & 15;
    int s = idx >> 9;

    float inv = powf(10000.f, -(float)(2 * i) / (float)ROT);
    float ang = (float)s * inv;
    float sn, cs;
    sincosf(ang, &sn, &cs);

    size_t base = (size_t)s * EMBED + h * HD + 2 * i;
    float q0 = q[base], q1 = q[base + 1];
    q[base]     = q0 * cs - q1 * sn;
    q[base + 1] = q1 * cs + q0 * sn;
    float k0 = k[base], k1 = k[base + 1];
    k[base]     = k0 * cs - k1 * sn;
    k[base + 1] = k1 * cs + k0 * sn;
}

// ==============================================================================
// Causal flash attention, fp32. One block = 64 query rows of one head.
// 256 threads: tm=tid/16 (4 q-rows), tn=tid%16.
// Scores: thread owns 4x4 tile of the 64x64 score block.
// O: thread owns rows tm*4..+4, d-cols {kk*64 + tn*4 .. +4} for kk=0..3.
// smem: Qs[64][256], Vs[64][256], Ks_t[64dd][68], Ss[64][68]  (165,888 B)
// ==============================================================================
#define ABM 64
#define ABN 64
#define ATTN_SMEM ((64*256 + 64*256 + 64*68 + 64*68) * 4)

__global__ __launch_bounds__(256, 1)
void attn_kernel(const float* __restrict__ Q, const float* __restrict__ K,
                 const float* __restrict__ V, float* __restrict__ O)
{
    extern __shared__ float sm[];
    float* Qs = sm;                       // [64][256]
    float* Vs = Qs + 64 * 256;            // [64][256]
    float* Ks = Vs + 64 * 256;            // transposed slab: Ks[dd][n], stride 68
    float* Ss = Ks + 64 * 68;             // p tile: [64][68]

    const int tid = threadIdx.x;
    const int tm  = tid >> 4;             // 0..15
    const int tn  = tid & 15;             // 0..15
    const int h   = blockIdx.y;
    const int m0  = blockIdx.x * ABM;
    const int cb  = h * HD;               // channel base for this head

    // load Q tile
#pragma unroll
    for (int it = 0; it < 16; it++) {
        int f   = it * 256 + tid;
        int row = f >> 6;
        int c4  = f & 63;
        *(float4*)&Qs[row * 256 + c4 * 4] =
            *(const float4*)&Q[(size_t)(m0 + row) * EMBED + cb + c4 * 4];
    }

    float o[4][16];
#pragma unroll
    for (int i = 0; i < 4; i++)
#pragma unroll
        for (int j = 0; j < 16; j++) o[i][j] = 0.f;
    float mrow[4], lrow[4];
#pragma unroll
    for (int i = 0; i < 4; i++) { mrow[i] = -1e30f; lrow[i] = 0.f; }

    for (int n0 = 0; n0 <= m0; n0 += ABN) {
        __syncthreads();   // protect Vs/Ss from previous iteration readers

        // load V tile [64][256]
#pragma unroll
        for (int it = 0; it < 16; it++) {
            int f   = it * 256 + tid;
            int row = f >> 6;
            int c4  = f & 63;
            *(float4*)&Vs[row * 256 + c4 * 4] =
                *(const float4*)&V[(size_t)(n0 + row) * EMBED + cb + c4 * 4];
        }

        float s[4][4];
#pragma unroll
        for (int i = 0; i < 4; i++)
#pragma unroll
            for (int j = 0; j < 4; j++) s[i][j] = 0.f;

        // ---- scores: 4 slabs of 64 d-dims ----
        for (int slab = 0; slab < 4; slab++) {
            __syncthreads();   // prev slab reads done (also covers Vs stores)
            {
                int n   = tid >> 2;
                int dd0 = (tid & 3) * 16;
                const float* kg = &K[(size_t)(n0 + n) * EMBED + cb + slab * 64 + dd0];
#pragma unroll
                for (int t = 0; t < 4; t++) {
                    float4 kv4 = *(const float4*)&kg[t * 4];
                    Ks[(dd0 + t * 4 + 0) * 68 + n] = kv4.x;
                    Ks[(dd0 + t * 4 + 1) * 68 + n] = kv4.y;
                    Ks[(dd0 + t * 4 + 2) * 68 + n] = kv4.z;
                    Ks[(dd0 + t * 4 + 3) * 68 + n] = kv4.w;
                }
            }
            __syncthreads();
            const int D0 = slab * 64;
#pragma unroll
            for (int dd4 = 0; dd4 < 16; dd4++) {
                float4 qv[4], kv[4];
#pragma unroll
                for (int i = 0; i < 4; i++)
                    qv[i] = *(float4*)&Qs[(tm * 4 + i) * 256 + D0 + dd4 * 4];
#pragma unroll
                for (int t = 0; t < 4; t++)
                    kv[t] = *(float4*)&Ks[(dd4 * 4 + t) * 68 + tn * 4];
#pragma unroll
                for (int i = 0; i < 4; i++) {
                    s[i][0] += qv[i].x * kv[0].x + qv[i].y * kv[1].x
                             + qv[i].z * kv[2].x + qv[i].w * kv[3].x;
                    s[i][1] += qv[i].x * kv[0].y + qv[i].y * kv[1].y
                             + qv[i].z * kv[2].y + qv[i].w * kv[3].y;
                    s[i][2] += qv[i].x * kv[0].z + qv[i].y * kv[1].z
                             + qv[i].z * kv[2].z + qv[i].w * kv[3].z;
                    s[i][3] += qv[i].x * kv[0].w + qv[i].y * kv[1].w
                             + qv[i].z * kv[2].w + qv[i].w * kv[3].w;
                }
            }
        }

        // ---- mask + scale (mask first like reference; -1e30 -> exp underflows)
        float p[4][4];
#pragma unroll
        for (int i = 0; i < 4; i++) {
            int mg = m0 + tm * 4 + i;
#pragma unroll
            for (int j = 0; j < 4; j++) {
                int ng = n0 + tn * 4 + j;
                p[i][j] = (ng <= mg) ? s[i][j] * 0.0625f : -1e30f;
            }
        }

        // ---- online softmax update ----
#pragma unroll
        for (int i = 0; i < 4; i++) {
            float mt = fmaxf(fmaxf(p[i][0], p[i][1]), fmaxf(p[i][2], p[i][3]));
#pragma unroll
            for (int off = 1; off < 16; off <<= 1)
                mt = fmaxf(mt, __shfl_xor_sync(0xffffffffu, mt, off));
            float mn   = fmaxf(mrow[i], mt);
            float corr = __expf(mrow[i] - mn);
            mrow[i] = mn;
            float ls = 0.f;
#pragma unroll
            for (int j = 0; j < 4; j++) {
                p[i][j] = __expf(p[i][j] - mn);
                ls += p[i][j];
            }
#pragma unroll
            for (int off = 1; off < 16; off <<= 1)
                ls += __shfl_xor_sync(0xffffffffu, ls, off);
            lrow[i] = lrow[i] * corr + ls;
#pragma unroll
            for (int j = 0; j < 16; j++) o[i][j] *= corr;
        }

        // ---- write p tile, then P @ V ----
#pragma unroll
        for (int i = 0; i < 4; i++)
            *(float4*)&Ss[(tm * 4 + i) * 68 + tn * 4] =
                make_float4(p[i][0], p[i][1], p[i][2], p[i][3]);
        __syncthreads();

#pragma unroll 4
        for (int n = 0; n < ABN; n++) {
            float pv[4];
#pragma unroll
            for (int i = 0; i < 4; i++) pv[i] = Ss[(tm * 4 + i) * 68 + n];
#pragma unroll
            for (int kk = 0; kk < 4; kk++) {
                float4 v4 = *(float4*)&Vs[n * 256 + kk * 64 + tn * 4];
#pragma unroll
                for (int i = 0; i < 4; i++) {
                    o[i][kk * 4 + 0] += pv[i] * v4.x;
                    o[i][kk * 4 + 1] += pv[i] * v4.y;
                    o[i][kk * 4 + 2] += pv[i] * v4.z;
                    o[i][kk * 4 + 3] += pv[i] * v4.w;
                }
            }
        }
    }

    // ---- normalize + write ----
#pragma unroll
    for (int i = 0; i < 4; i++) {
        float inv = 1.f / lrow[i];
        size_t rbase = (size_t)(m0 + tm * 4 + i) * EMBED + cb;
#pragma unroll
        for (int kk = 0; kk < 4; kk++) {
            *(float4*)&O[rbase + kk * 64 + tn * 4] =
                make_float4(o[i][kk * 4 + 0] * inv, o[i][kk * 4 + 1] * inv,
                            o[i][kk * 4 + 2] * inv, o[i][kk * 4 + 3] * inv);
        }
    }
}

// ==============================================================================
// launch
// ==============================================================================
extern "C" void kernel_launch(void* const* d_in, const int* in_sizes, int n_in,
                              void* d_out, int out_size)
{
    (void)in_sizes; (void)n_in; (void)out_size;
    const float* X  = (const float*)d_in[0];
    const float* Wq = (const float*)d_in[1];
    const float* Wk = (const float*)d_in[2];
    const float* Wv = (const float*)d_in[3];
    const float* Wo = (const float*)d_in[4];
    float* out = (float*)d_out;

    float *q, *k, *v, *ao;
    cudaGetSymbolAddress((void**)&q,  g_q);
    cudaGetSymbolAddress((void**)&k,  g_k);
    cudaGetSymbolAddress((void**)&v,  g_v);
    cudaGetSymbolAddress((void**)&ao, g_ao);

    cudaFuncSetAttribute(attn_kernel,
                         cudaFuncAttributeMaxDynamicSharedMemorySize, ATTN_SMEM);

    dim3 gg(4096 / GBN, 4096 / GBM);
    gemm_nt<<<gg, 256>>>(X, Wq, q);
    gemm_nt<<<gg, 256>>>(X, Wk, k);
    gemm_nt<<<gg, 256>>>(X, Wv, v);

    rope_kernel<<<(SEQ * HEADS * 32) / 256, 256>>>(q, k);

    dim3 ga(SEQ / ABM, HEADS);
    attn_kernel<<<ga, 256, ATTN_SMEM>>>(q, k, v, ao);

    gemm_nt<<<gg, 256>>>(ao, Wo, out);
}

// round 2
// speedup vs baseline: 1.8976x; 1.8976x over previous
#include <cuda_runtime.h>
#include <math.h>
#include <stdint.h>

#define SEQ   4096
#define EMBED 4096
#define HEADS 16
#define HD    256
#define ROT   64

// ---------------- scratch (allocation-free rule: __device__ globals) ----------
__device__ float g_q [SEQ * EMBED];
__device__ float g_k [SEQ * EMBED];
__device__ float g_v [SEQ * EMBED];
__device__ float g_ao[SEQ * EMBED];

// ==============================================================================
// tf32 tensor-core GEMM (NT): C[M,N] = A[M,K] * B[N,K]^T, 4096^3
// 128x128x32 block tile, 8 warps (2x4), warp tile 64x32 (4x4 m16n8k8 tiles),
// cp.async double-buffered smem, KS=36 padding -> conflict-free fragment LDS.
// Fragments rounded with cvt.rna.tf32.f32 (RNA, not truncation) before HMMA.
// ==============================================================================
#define BM 128
#define BN 128
#define BK 32
#define KS 36                     // padded k-stride (floats)
#define STAGE_F (BM * KS)         // floats per stage per matrix
#define GEMM_SMEM (4 * STAGE_F * 4)   // 2 stages * (A+B) * 4B = 73728

__device__ __forceinline__ uint32_t f2tf(float x) {
    uint32_t r;
    asm("cvt.rna.tf32.f32 %0, %1;" : "=r"(r) : "f"(x));
    return r;
}

__device__ __forceinline__ void cp16(uint32_t dst_smem, const float* src) {
    asm volatile("cp.async.cg.shared.global [%0], [%1], 16;"
                 :: "r"(dst_smem), "l"(src));
}

__global__ __launch_bounds__(256, 2)
void gemm_tf32(const float* __restrict__ A, const float* __restrict__ B,
               float* __restrict__ C)
{
    extern __shared__ float sm[];
    float* As = sm;                   // [2][BM][KS]
    float* Bs = sm + 2 * STAGE_F;     // [2][BN][KS]

    const int tid  = threadIdx.x;
    const int lane = tid & 31;
    const int warp = tid >> 5;
    const int wm   = warp & 1;        // 0..1  -> 64-row slab
    const int wn   = warp >> 1;       // 0..3  -> 32-col slab
    const int g    = lane >> 2;       // 0..7
    const int t4   = lane & 3;        // 0..3
    const int m0   = blockIdx.y * BM;
    const int n0   = blockIdx.x * BN;

    const int ldrow = tid >> 3;       // 0..31 base row
    const int ldc4  = tid & 7;        // 16B chunk within 32-float row

    const uint32_t sa_base = (uint32_t)__cvta_generic_to_shared(As);
    const uint32_t sb_base = (uint32_t)__cvta_generic_to_shared(Bs);

    float acc[4][4][4];
#pragma unroll
    for (int i = 0; i < 4; i++)
#pragma unroll
        for (int j = 0; j < 4; j++)
#pragma unroll
            for (int r = 0; r < 4; r++) acc[i][j][r] = 0.f;

    const int NT = 4096 / BK;         // 128 k-tiles

    // ---- prologue: stage 0 ----
    {
#pragma unroll
        for (int i = 0; i < 4; i++) {
            int row = ldrow + 32 * i;
            cp16(sa_base + (row * KS + ldc4 * 4) * 4,
                 &A[(size_t)(m0 + row) * 4096 + ldc4 * 4]);
            cp16(sb_base + (row * KS + ldc4 * 4) * 4,
                 &B[(size_t)(n0 + row) * 4096 + ldc4 * 4]);
        }
        asm volatile("cp.async.commit_group;");
    }

    for (int t = 0; t < NT; t++) {
        const int cur = t & 1;
        if (t + 1 < NT) {
            const int nxt = cur ^ 1;
            const int kt  = (t + 1) * BK;
#pragma unroll
            for (int i = 0; i < 4; i++) {
                int row = ldrow + 32 * i;
                cp16(sa_base + (nxt * STAGE_F + row * KS + ldc4 * 4) * 4,
                     &A[(size_t)(m0 + row) * 4096 + kt + ldc4 * 4]);
                cp16(sb_base + (nxt * STAGE_F + row * KS + ldc4 * 4) * 4,
                     &B[(size_t)(n0 + row) * 4096 + kt + ldc4 * 4]);
            }
            asm volatile("cp.async.commit_group;");
            asm volatile("cp.async.wait_group 1;");
        } else {
            asm volatile("cp.async.wait_group 0;");
        }
        __syncthreads();

        const float* Ab = As + cur * STAGE_F + (wm * 64) * KS;
        const float* Bb = Bs + cur * STAGE_F + (wn * 32) * KS;

#pragma unroll
        for (int kk = 0; kk < BK; kk += 8) {
            uint32_t af[4][4], bf[4][2];
#pragma unroll
            for (int mt = 0; mt < 4; mt++) {
                const float* p = Ab + (mt * 16 + g) * KS + kk + t4;
                af[mt][0] = f2tf(p[0]);
                af[mt][1] = f2tf(p[8 * KS]);
                af[mt][2] = f2tf(p[4]);
                af[mt][3] = f2tf(p[8 * KS + 4]);
            }
#pragma unroll
            for (int nt = 0; nt < 4; nt++) {
                const float* p = Bb + (nt * 8 + g) * KS + kk + t4;
                bf[nt][0] = f2tf(p[0]);
                bf[nt][1] = f2tf(p[4]);
            }
#pragma unroll
            for (int mt = 0; mt < 4; mt++)
#pragma unroll
                for (int nt = 0; nt < 4; nt++)
                    asm volatile(
                        "mma.sync.aligned.m16n8k8.row.col.f32.tf32.tf32.f32 "
                        "{%0,%1,%2,%3}, {%4,%5,%6,%7}, {%8,%9}, {%0,%1,%2,%3};"
                        : "+f"(acc[mt][nt][0]), "+f"(acc[mt][nt][1]),
                          "+f"(acc[mt][nt][2]), "+f"(acc[mt][nt][3])
                        : "r"(af[mt][0]), "r"(af[mt][1]),
                          "r"(af[mt][2]), "r"(af[mt][3]),
                          "r"(bf[nt][0]), "r"(bf[nt][1]));
        }
        __syncthreads();
    }

    // ---- epilogue ----
#pragma unroll
    for (int mt = 0; mt < 4; mt++) {
        int r0 = m0 + wm * 64 + mt * 16 + g;
#pragma unroll
        for (int nt = 0; nt < 4; nt++) {
            int col = n0 + wn * 32 + nt * 8 + t4 * 2;
            *(float2*)&C[(size_t)r0 * 4096 + col] =
                make_float2(acc[mt][nt][0], acc[mt][nt][1]);
            *(float2*)&C[(size_t)(r0 + 8) * 4096 + col] =
                make_float2(acc[mt][nt][2], acc[mt][nt][3]);
        }
    }
}

// ==============================================================================
// RoPE on first ROT=64 dims of each head, applied in place to Q and K.
// ==============================================================================
__global__ void rope_kernel(float* __restrict__ q, float* __restrict__ k)
{
    int idx = blockIdx.x * blockDim.x + threadIdx.x;
    int i = idx & 31;
    int h = (idx >> 5) & 15;
    int s = idx >> 9;

    float inv = powf(10000.f, -(float)(2 * i) / (float)ROT);
    float ang = (float)s * inv;
    float sn, cs;
    sincosf(ang, &sn, &cs);

    size_t base = (size_t)s * EMBED + h * HD + 2 * i;
    float q0 = q[base], q1 = q[base + 1];
    q[base]     = q0 * cs - q1 * sn;
    q[base + 1] = q1 * cs + q0 * sn;
    float k0 = k[base], k1 = k[base + 1];
    k[base]     = k0 * cs - k1 * sn;
    k[base + 1] = k1 * cs + k0 * sn;
}

// ==============================================================================
// Causal flash attention, fp32 (unchanged this round; next target).
// ==============================================================================
#define ABM 64
#define ABN 64
#define ATTN_SMEM ((64*256 + 64*256 + 64*68 + 64*68) * 4)

__global__ __launch_bounds__(256, 1)
void attn_kernel(const float* __restrict__ Q, const float* __restrict__ K,
                 const float* __restrict__ V, float* __restrict__ O)
{
    extern __shared__ float smf[];
    float* Qs = smf;
    float* Vs = Qs + 64 * 256;
    float* Ks = Vs + 64 * 256;
    float* Ss = Ks + 64 * 68;

    const int tid = threadIdx.x;
    const int tm  = tid >> 4;
    const int tn  = tid & 15;
    const int h   = blockIdx.y;
    const int m0  = blockIdx.x * ABM;
    const int cb  = h * HD;

#pragma unroll
    for (int it = 0; it < 16; it++) {
        int f   = it * 256 + tid;
        int row = f >> 6;
        int c4  = f & 63;
        *(float4*)&Qs[row * 256 + c4 * 4] =
            *(const float4*)&Q[(size_t)(m0 + row) * EMBED + cb + c4 * 4];
    }

    float o[4][16];
#pragma unroll
    for (int i = 0; i < 4; i++)
#pragma unroll
        for (int j = 0; j < 16; j++) o[i][j] = 0.f;
    float mrow[4], lrow[4];
#pragma unroll
    for (int i = 0; i < 4; i++) { mrow[i] = -1e30f; lrow[i] = 0.f; }

    for (int n0 = 0; n0 <= m0; n0 += ABN) {
        __syncthreads();

#pragma unroll
        for (int it = 0; it < 16; it++) {
            int f   = it * 256 + tid;
            int row = f >> 6;
            int c4  = f & 63;
            *(float4*)&Vs[row * 256 + c4 * 4] =
                *(const float4*)&V[(size_t)(n0 + row) * EMBED + cb + c4 * 4];
        }

        float s[4][4];
#pragma unroll
        for (int i = 0; i < 4; i++)
#pragma unroll
            for (int j = 0; j < 4; j++) s[i][j] = 0.f;

        for (int slab = 0; slab < 4; slab++) {
            __syncthreads();
            {
                int n   = tid >> 2;
                int dd0 = (tid & 3) * 16;
                const float* kg = &K[(size_t)(n0 + n) * EMBED + cb + slab * 64 + dd0];
#pragma unroll
                for (int t = 0; t < 4; t++) {
                    float4 kv4 = *(const float4*)&kg[t * 4];
                    Ks[(dd0 + t * 4 + 0) * 68 + n] = kv4.x;
                    Ks[(dd0 + t * 4 + 1) * 68 + n] = kv4.y;
                    Ks[(dd0 + t * 4 + 2) * 68 + n] = kv4.z;
                    Ks[(dd0 + t * 4 + 3) * 68 + n] = kv4.w;
                }
            }
            __syncthreads();
            const int D0 = slab * 64;
#pragma unroll
            for (int dd4 = 0; dd4 < 16; dd4++) {
                float4 qv[4], kv[4];
#pragma unroll
                for (int i = 0; i < 4; i++)
                    qv[i] = *(float4*)&Qs[(tm * 4 + i) * 256 + D0 + dd4 * 4];
#pragma unroll
                for (int t = 0; t < 4; t++)
                    kv[t] = *(float4*)&Ks[(dd4 * 4 + t) * 68 + tn * 4];
#pragma unroll
                for (int i = 0; i < 4; i++) {
                    s[i][0] += qv[i].x * kv[0].x + qv[i].y * kv[1].x
                             + qv[i].z * kv[2].x + qv[i].w * kv[3].x;
                    s[i][1] += qv[i].x * kv[0].y + qv[i].y * kv[1].y
                             + qv[i].z * kv[2].y + qv[i].w * kv[3].y;
                    s[i][2] += qv[i].x * kv[0].z + qv[i].y * kv[1].z
                             + qv[i].z * kv[2].z + qv[i].w * kv[3].z;
                    s[i][3] += qv[i].x * kv[0].w + qv[i].y * kv[1].w
                             + qv[i].z * kv[2].w + qv[i].w * kv[3].w;
                }
            }
        }

        float p[4][4];
#pragma unroll
        for (int i = 0; i < 4; i++) {
            int mg = m0 + tm * 4 + i;
#pragma unroll
            for (int j = 0; j < 4; j++) {
                int ng = n0 + tn * 4 + j;
                p[i][j] = (ng <= mg) ? s[i][j] * 0.0625f : -1e30f;
            }
        }

#pragma unroll
        for (int i = 0; i < 4; i++) {
            float mt = fmaxf(fmaxf(p[i][0], p[i][1]), fmaxf(p[i][2], p[i][3]));
#pragma unroll
            for (int off = 1; off < 16; off <<= 1)
                mt = fmaxf(mt, __shfl_xor_sync(0xffffffffu, mt, off));
            float mn   = fmaxf(mrow[i], mt);
            float corr = __expf(mrow[i] - mn);
            mrow[i] = mn;
            float ls = 0.f;
#pragma unroll
            for (int j = 0; j < 4; j++) {
                p[i][j] = __expf(p[i][j] - mn);
                ls += p[i][j];
            }
#pragma unroll
            for (int off = 1; off < 16; off <<= 1)
                ls += __shfl_xor_sync(0xffffffffu, ls, off);
            lrow[i] = lrow[i] * corr + ls;
#pragma unroll
            for (int j = 0; j < 16; j++) o[i][j] *= corr;
        }

#pragma unroll
        for (int i = 0; i < 4; i++)
            *(float4*)&Ss[(tm * 4 + i) * 68 + tn * 4] =
                make_float4(p[i][0], p[i][1], p[i][2], p[i][3]);
        __syncthreads();

#pragma unroll 4
        for (int n = 0; n < ABN; n++) {
            float pv[4];
#pragma unroll
            for (int i = 0; i < 4; i++) pv[i] = Ss[(tm * 4 + i) * 68 + n];
#pragma unroll
            for (int kk = 0; kk < 4; kk++) {
                float4 v4 = *(float4*)&Vs[n * 256 + kk * 64 + tn * 4];
#pragma unroll
                for (int i = 0; i < 4; i++) {
                    o[i][kk * 4 + 0] += pv[i] * v4.x;
                    o[i][kk * 4 + 1] += pv[i] * v4.y;
                    o[i][kk * 4 + 2] += pv[i] * v4.z;
                    o[i][kk * 4 + 3] += pv[i] * v4.w;
                }
            }
        }
    }

#pragma unroll
    for (int i = 0; i < 4; i++) {
        float inv = 1.f / lrow[i];
        size_t rbase = (size_t)(m0 + tm * 4 + i) * EMBED + cb;
#pragma unroll
        for (int kk = 0; kk < 4; kk++) {
            *(float4*)&O[rbase + kk * 64 + tn * 4] =
                make_float4(o[i][kk * 4 + 0] * inv, o[i][kk * 4 + 1] * inv,
                            o[i][kk * 4 + 2] * inv, o[i][kk * 4 + 3] * inv);
        }
    }
}

// ==============================================================================
// launch
// ==============================================================================
extern "C" void kernel_launch(void* const* d_in, const int* in_sizes, int n_in,
                              void* d_out, int out_size)
{
    (void)in_sizes; (void)n_in; (void)out_size;
    const float* X  = (const float*)d_in[0];
    const float* Wq = (const float*)d_in[1];
    const float* Wk = (const float*)d_in[2];
    const float* Wv = (const float*)d_in[3];
    const float* Wo = (const float*)d_in[4];
    float* out = (float*)d_out;

    float *q, *k, *v, *ao;
    cudaGetSymbolAddress((void**)&q,  g_q);
    cudaGetSymbolAddress((void**)&k,  g_k);
    cudaGetSymbolAddress((void**)&v,  g_v);
    cudaGetSymbolAddress((void**)&ao, g_ao);

    cudaFuncSetAttribute(gemm_tf32,
                         cudaFuncAttributeMaxDynamicSharedMemorySize, GEMM_SMEM);
    cudaFuncSetAttribute(attn_kernel,
                         cudaFuncAttributeMaxDynamicSharedMemorySize, ATTN_SMEM);

    dim3 gg(4096 / BN, 4096 / BM);
    gemm_tf32<<<gg, 256, GEMM_SMEM>>>(X, Wq, q);
    gemm_tf32<<<gg, 256, GEMM_SMEM>>>(X, Wk, k);
    gemm_tf32<<<gg, 256, GEMM_SMEM>>>(X, Wv, v);

    rope_kernel<<<(SEQ * HEADS * 32) / 256, 256>>>(q, k);

    dim3 ga(SEQ / ABM, HEADS);
    attn_kernel<<<ga, 256, ATTN_SMEM>>>(q, k, v, ao);

    gemm_tf32<<<gg, 256, GEMM_SMEM>>>(ao, Wo, out);
}

// round 4
// speedup vs baseline: 3.2079x; 1.6905x over previous
#include <cuda_runtime.h>
#include <cuda_bf16.h>
#include <cuda_fp16.h>
#include <math.h>
#include <stdint.h>

#define SEQ   4096
#define EMBED 4096
#define HEADS 16
#define HD    256
#define ROT   64
#define NELEM (SEQ * EMBED)

// ---------------- scratch (allocation-free rule: __device__ globals) ----------
__device__ float g_q [NELEM];
__device__ float g_k [NELEM];
__device__ float g_v [NELEM];
__device__ float g_ao[NELEM];
__device__ __nv_bfloat16 g_qhi[NELEM];
__device__ __nv_bfloat16 g_qlo[NELEM];
__device__ __nv_bfloat16 g_khi[NELEM];
__device__ __nv_bfloat16 g_klo[NELEM];
__device__ __half        g_vh [NELEM];

// ==============================================================================
// helpers
// ==============================================================================
__device__ __forceinline__ uint32_t f2tf(float x) {
    uint32_t r;
    asm("cvt.rna.tf32.f32 %0, %1;" : "=r"(r) : "f"(x));
    return r;
}

__device__ __forceinline__ void cp16(uint32_t dst, const void* src) {
    asm volatile("cp.async.cg.shared.global [%0], [%1], 16;" :: "r"(dst), "l"(src));
}

__device__ __forceinline__ void ldsm4(uint32_t* r, uint32_t a) {
    asm volatile("ldmatrix.sync.aligned.m8n8.x4.shared.b16 {%0,%1,%2,%3}, [%4];"
                 : "=r"(r[0]), "=r"(r[1]), "=r"(r[2]), "=r"(r[3]) : "r"(a));
}

__device__ __forceinline__ void ldsm4t(uint32_t* r, uint32_t a) {
    asm volatile("ldmatrix.sync.aligned.m8n8.x4.trans.shared.b16 {%0,%1,%2,%3}, [%4];"
                 : "=r"(r[0]), "=r"(r[1]), "=r"(r[2]), "=r"(r[3]) : "r"(a));
}

__device__ __forceinline__ void mma_bf16(float* c, const uint32_t* a,
                                         uint32_t b0, uint32_t b1) {
    asm volatile(
        "mma.sync.aligned.m16n8k16.row.col.f32.bf16.bf16.f32 "
        "{%0,%1,%2,%3}, {%4,%5,%6,%7}, {%8,%9}, {%0,%1,%2,%3};"
        : "+f"(c[0]), "+f"(c[1]), "+f"(c[2]), "+f"(c[3])
        : "r"(a[0]), "r"(a[1]), "r"(a[2]), "r"(a[3]), "r"(b0), "r"(b1));
}

__device__ __forceinline__ void mma_f16(float* c, const uint32_t* a,
                                        uint32_t b0, uint32_t b1) {
    asm volatile(
        "mma.sync.aligned.m16n8k16.row.col.f32.f16.f16.f32 "
        "{%0,%1,%2,%3}, {%4,%5,%6,%7}, {%8,%9}, {%0,%1,%2,%3};"
        : "+f"(c[0]), "+f"(c[1]), "+f"(c[2]), "+f"(c[3])
        : "r"(a[0]), "r"(a[1]), "r"(a[2]), "r"(a[3]), "r"(b0), "r"(b1));
}

// ==============================================================================
// tf32 tensor-core GEMM (NT) -- unchanged from round 2 (known good, 76% of peak)
// ==============================================================================
#define BM 128
#define BN 128
#define BK 32
#define KS 36
#define STAGE_F (BM * KS)
#define GEMM_SMEM (4 * STAGE_F * 4)

__global__ __launch_bounds__(256, 2)
void gemm_tf32(const float* __restrict__ A, const float* __restrict__ B,
               float* __restrict__ C)
{
    extern __shared__ float smg[];
    float* As = smg;
    float* Bs = smg + 2 * STAGE_F;

    const int tid  = threadIdx.x;
    const int lane = tid & 31;
    const int warp = tid >> 5;
    const int wm   = warp & 1;
    const int wn   = warp >> 1;
    const int g    = lane >> 2;
    const int t4   = lane & 3;
    const int m0   = blockIdx.y * BM;
    const int n0   = blockIdx.x * BN;

    const int ldrow = tid >> 3;
    const int ldc4  = tid & 7;

    const uint32_t sa_base = (uint32_t)__cvta_generic_to_shared(As);
    const uint32_t sb_base = (uint32_t)__cvta_generic_to_shared(Bs);

    float acc[4][4][4];
#pragma unroll
    for (int i = 0; i < 4; i++)
#pragma unroll
        for (int j = 0; j < 4; j++)
#pragma unroll
            for (int r = 0; r < 4; r++) acc[i][j][r] = 0.f;

    const int NT = 4096 / BK;

    {
#pragma unroll
        for (int i = 0; i < 4; i++) {
            int row = ldrow + 32 * i;
            cp16(sa_base + (row * KS + ldc4 * 4) * 4,
                 &A[(size_t)(m0 + row) * 4096 + ldc4 * 4]);
            cp16(sb_base + (row * KS + ldc4 * 4) * 4,
                 &B[(size_t)(n0 + row) * 4096 + ldc4 * 4]);
        }
        asm volatile("cp.async.commit_group;");
    }

    for (int t = 0; t < NT; t++) {
        const int cur = t & 1;
        if (t + 1 < NT) {
            const int nxt = cur ^ 1;
            const int kt  = (t + 1) * BK;
#pragma unroll
            for (int i = 0; i < 4; i++) {
                int row = ldrow + 32 * i;
                cp16(sa_base + (nxt * STAGE_F + row * KS + ldc4 * 4) * 4,
                     &A[(size_t)(m0 + row) * 4096 + kt + ldc4 * 4]);
                cp16(sb_base + (nxt * STAGE_F + row * KS + ldc4 * 4) * 4,
                     &B[(size_t)(n0 + row) * 4096 + kt + ldc4 * 4]);
            }
            asm volatile("cp.async.commit_group;");
            asm volatile("cp.async.wait_group 1;");
        } else {
            asm volatile("cp.async.wait_group 0;");
        }
        __syncthreads();

        const float* Ab = As + cur * STAGE_F + (wm * 64) * KS;
        const float* Bb = Bs + cur * STAGE_F + (wn * 32) * KS;

#pragma unroll
        for (int kk = 0; kk < BK; kk += 8) {
            uint32_t af[4][4], bf[4][2];
#pragma unroll
            for (int mt = 0; mt < 4; mt++) {
                const float* p = Ab + (mt * 16 + g) * KS + kk + t4;
                af[mt][0] = f2tf(p[0]);
                af[mt][1] = f2tf(p[8 * KS]);
                af[mt][2] = f2tf(p[4]);
                af[mt][3] = f2tf(p[8 * KS + 4]);
            }
#pragma unroll
            for (int nt = 0; nt < 4; nt++) {
                const float* p = Bb + (nt * 8 + g) * KS + kk + t4;
                bf[nt][0] = f2tf(p[0]);
                bf[nt][1] = f2tf(p[4]);
            }
#pragma unroll
            for (int mt = 0; mt < 4; mt++)
#pragma unroll
                for (int nt = 0; nt < 4; nt++)
                    asm volatile(
                        "mma.sync.aligned.m16n8k8.row.col.f32.tf32.tf32.f32 "
                        "{%0,%1,%2,%3}, {%4,%5,%6,%7}, {%8,%9}, {%0,%1,%2,%3};"
                        : "+f"(acc[mt][nt][0]), "+f"(acc[mt][nt][1]),
                          "+f"(acc[mt][nt][2]), "+f"(acc[mt][nt][3])
                        : "r"(af[mt][0]), "r"(af[mt][1]),
                          "r"(af[mt][2]), "r"(af[mt][3]),
                          "r"(bf[nt][0]), "r"(bf[nt][1]));
        }
        __syncthreads();
    }

#pragma unroll
    for (int mt = 0; mt < 4; mt++) {
        int r0 = m0 + wm * 64 + mt * 16 + g;
#pragma unroll
        for (int nt = 0; nt < 4; nt++) {
            int col = n0 + wn * 32 + nt * 8 + t4 * 2;
            *(float2*)&C[(size_t)r0 * 4096 + col] =
                make_float2(acc[mt][nt][0], acc[mt][nt][1]);
            *(float2*)&C[(size_t)(r0 + 8) * 4096 + col] =
                make_float2(acc[mt][nt][2], acc[mt][nt][3]);
        }
    }
}

// ==============================================================================
// prep: RoPE on q,k (first 64 dims/head) + emit bf16 hi/lo planes (q,k) and
// fp16 plane (v). One float4 per thread per tensor.
// ==============================================================================
__global__ void prep_qkv(const float* __restrict__ q, const float* __restrict__ k,
                         const float* __restrict__ v,
                         __nv_bfloat16* __restrict__ qhi, __nv_bfloat16* __restrict__ qlo,
                         __nv_bfloat16* __restrict__ khi, __nv_bfloat16* __restrict__ klo,
                         __half* __restrict__ vh)
{
    const int i = blockIdx.x * blockDim.x + threadIdx.x;    // float4 index
    const int e = i * 4;
    const int s = e >> 12;
    const int hd = e & 255;

    float4 qv = ((const float4*)q)[i];
    float4 kv = ((const float4*)k)[i];
    float4 vv = ((const float4*)v)[i];

    if (hd < ROT) {
        const int j0 = hd >> 1;
        float a0 = (float)s * powf(10000.f, -(float)j0 / 32.f);
        float a1 = (float)s * powf(10000.f, -(float)(j0 + 1) / 32.f);
        float s0, c0, s1, c1;
        sincosf(a0, &s0, &c0);
        sincosf(a1, &s1, &c1);
        float x, y;
        x = qv.x; y = qv.y; qv.x = x * c0 - y * s0; qv.y = y * c0 + x * s0;
        x = qv.z; y = qv.w; qv.z = x * c1 - y * s1; qv.w = y * c1 + x * s1;
        x = kv.x; y = kv.y; kv.x = x * c0 - y * s0; kv.y = y * c0 + x * s0;
        x = kv.z; y = kv.w; kv.z = x * c1 - y * s1; kv.w = y * c1 + x * s1;
    }

#define SPLIT2(vx, vy, hi2, lo2) {                                         \
        __nv_bfloat16 _h0 = __float2bfloat16_rn(vx);                       \
        __nv_bfloat16 _h1 = __float2bfloat16_rn(vy);                       \
        hi2 = __nv_bfloat162(_h0, _h1);                                    \
        lo2 = __nv_bfloat162(__float2bfloat16_rn((vx) - __bfloat162float(_h0)), \
                             __float2bfloat16_rn((vy) - __bfloat162float(_h1))); }

    __nv_bfloat162 h2, l2;
    SPLIT2(qv.x, qv.y, h2, l2);
    ((__nv_bfloat162*)qhi)[2 * i]     = h2; ((__nv_bfloat162*)qlo)[2 * i]     = l2;
    SPLIT2(qv.z, qv.w, h2, l2);
    ((__nv_bfloat162*)qhi)[2 * i + 1] = h2; ((__nv_bfloat162*)qlo)[2 * i + 1] = l2;
    SPLIT2(kv.x, kv.y, h2, l2);
    ((__nv_bfloat162*)khi)[2 * i]     = h2; ((__nv_bfloat162*)klo)[2 * i]     = l2;
    SPLIT2(kv.z, kv.w, h2, l2);
    ((__nv_bfloat162*)khi)[2 * i + 1] = h2; ((__nv_bfloat162*)klo)[2 * i + 1] = l2;

    ((half2*)vh)[2 * i]     = __floats2half2_rn(vv.x, vv.y);
    ((half2*)vh)[2 * i + 1] = __floats2half2_rn(vv.z, vv.w);
#undef SPLIT2
}

// ==============================================================================
// Tensor-core causal flash attention.
// Block = 64 q-rows of one head, 8 warps (256 thr).
// Warps 0-3: d 0-127 half of QK + softmax owner; warps 4-7: d 128-255 half,
// partial scores passed through smem. PV: warp (w&3) rows slice, (w>>2) d-half.
// QK: bf16 hi/lo planes, 3 mma products. PV: fp16.
// smem rows padded to 528B (Q/K/V) and 144B (P) -> conflict-free ldmatrix.
// ==============================================================================
#define QSTR 528
#define PSTR 144
#define S_QHI 0
#define S_QLO 33792
#define S_KHI 67584
#define S_KLO 101376
#define S_V   135168
#define S_SB  168960
#define S_P   186368
#define S_CORR 195584
#define S_LINV 195840
#define ATT_SMEM 196096

__global__ __launch_bounds__(256, 1)
void attn_mma(const __nv_bfloat16* __restrict__ Qhi, const __nv_bfloat16* __restrict__ Qlo,
              const __nv_bfloat16* __restrict__ Khi, const __nv_bfloat16* __restrict__ Klo,
              const __half* __restrict__ Vh, float* __restrict__ O)
{
    extern __shared__ __align__(16) char sm[];
    const uint32_t sb = (uint32_t)__cvta_generic_to_shared(sm);
    float* SBf    = (float*)(sm + S_SB);
    float* corr_s = (float*)(sm + S_CORR);
    float* linv_s = (float*)(sm + S_LINV);

    const int tid   = threadIdx.x;
    const int lane  = tid & 31;
    const int wid   = tid >> 5;
    const int grp   = wid >> 2;            // 0: d 0-127 + softmax, 1: d 128-255
    const int slice = (wid & 3) * 16;      // q-row slice within block
    const int g     = lane >> 2;
    const int qd    = lane & 3;

    const int h    = blockIdx.y;
    const int m0   = ((int)gridDim.x - 1 - (int)blockIdx.x) * 64;  // heavy blocks first
    const int cb   = h * HD;
    const int doff = grp * 128;

    // ---- persistent Q tile (hi/lo planes) ----
    for (int f = tid; f < 2048; f += 256) {
        const int r = f >> 5, c = f & 31;
        const size_t go = (size_t)(m0 + r) * EMBED + cb + c * 8;
        cp16(sb + S_QHI + r * QSTR + c * 16, Qhi + go);
        cp16(sb + S_QLO + r * QSTR + c * 16, Qlo + go);
    }

    float of[16][4];
#pragma unroll
    for (int j = 0; j < 16; j++)
#pragma unroll
        for (int r = 0; r < 4; r++) of[j][r] = 0.f;
    float mr0 = -1e30f, mr1 = -1e30f, l0 = 0.f, l1 = 0.f;

    const int ntl = m0 / 64 + 1;
    for (int t = 0; t < ntl; t++) {
        const int n0 = t * 64;
        __syncthreads();   // protect K/V/P/SB from previous iteration readers

        // ---- load K planes + V tile ----
        for (int f = tid; f < 2048; f += 256) {
            const int r = f >> 5, c = f & 31;
            const size_t go = (size_t)(n0 + r) * EMBED + cb + c * 8;
            cp16(sb + S_KHI + r * QSTR + c * 16, Khi + go);
            cp16(sb + S_KLO + r * QSTR + c * 16, Klo + go);
            cp16(sb + S_V   + r * QSTR + c * 16, Vh  + go);
        }
        asm volatile("cp.async.commit_group;");
        asm volatile("cp.async.wait_group 0;");
        __syncthreads();

        // ---- QK^T over this group's d-half (bf16 hi/lo, 3 products) ----
        float sf[8][4];
#pragma unroll
        for (int nt = 0; nt < 8; nt++)
#pragma unroll
            for (int r = 0; r < 4; r++) sf[nt][r] = 0.f;

        const uint32_t qa = sb + S_QHI + (slice + (lane & 15)) * QSTR + (lane >> 4) * 16;
#pragma unroll
        for (int kc = 0; kc < 8; kc++) {
            const int dby = (doff + kc * 16) * 2;
            uint32_t qh[4], ql[4];
            ldsm4(qh, qa + dby);
            ldsm4(ql, qa + dby + (S_QLO - S_QHI));
#pragma unroll
            for (int kg = 0; kg < 4; kg++) {
                const int key = kg * 16 + (lane & 7) + ((lane >> 4) & 1) * 8;
                const uint32_t ba = sb + S_KHI + key * QSTR + dby + ((lane >> 3) & 1) * 16;
                uint32_t kh[4], kl[4];
                ldsm4(kh, ba);
                ldsm4(kl, ba + (S_KLO - S_KHI));
                mma_bf16(sf[2 * kg],     qh, kh[0], kh[1]);
                mma_bf16(sf[2 * kg],     qh, kl[0], kl[1]);
                mma_bf16(sf[2 * kg],     ql, kh[0], kh[1]);
                mma_bf16(sf[2 * kg + 1], qh, kh[2], kh[3]);
                mma_bf16(sf[2 * kg + 1], qh, kl[2], kl[3]);
                mma_bf16(sf[2 * kg + 1], ql, kh[2], kh[3]);
            }
        }

        // ---- group B publishes its partial scores ----
        if (grp == 1) {
#pragma unroll
            for (int nt = 0; nt < 8; nt++) {
                const int col = nt * 8 + qd * 2;
                *(float2*)&SBf[(slice + g) * 68 + col]     = make_float2(sf[nt][0], sf[nt][1]);
                *(float2*)&SBf[(slice + g + 8) * 68 + col] = make_float2(sf[nt][2], sf[nt][3]);
            }
        }
        __syncthreads();

        // ---- group A: combine, mask+scale, online softmax, emit P (fp16) ----
        if (grp == 0) {
            const int row0 = m0 + slice + g, row1 = row0 + 8;
            float px0 = -1e30f, px1 = -1e30f;
#pragma unroll
            for (int nt = 0; nt < 8; nt++) {
                const int col = nt * 8 + qd * 2;
                const float2 b0 = *(float2*)&SBf[(slice + g) * 68 + col];
                const float2 b1 = *(float2*)&SBf[(slice + g + 8) * 68 + col];
                const int cg = n0 + col;
                sf[nt][0] = (cg     <= row0) ? (sf[nt][0] + b0.x) * 0.0625f : -1e30f;
                sf[nt][1] = (cg + 1 <= row0) ? (sf[nt][1] + b0.y) * 0.0625f : -1e30f;
                sf[nt][2] = (cg     <= row1) ? (sf[nt][2] + b1.x) * 0.0625f : -1e30f;
                sf[nt][3] = (cg + 1 <= row1) ? (sf[nt][3] + b1.y) * 0.0625f : -1e30f;
                px0 = fmaxf(px0, fmaxf(sf[nt][0], sf[nt][1]));
                px1 = fmaxf(px1, fmaxf(sf[nt][2], sf[nt][3]));
            }
            px0 = fmaxf(px0, __shfl_xor_sync(0xffffffffu, px0, 1));
            px0 = fmaxf(px0, __shfl_xor_sync(0xffffffffu, px0, 2));
            px1 = fmaxf(px1, __shfl_xor_sync(0xffffffffu, px1, 1));
            px1 = fmaxf(px1, __shfl_xor_sync(0xffffffffu, px1, 2));
            const float mn0 = fmaxf(mr0, px0), mn1 = fmaxf(mr1, px1);
            const float cr0 = __expf(mr0 - mn0), cr1 = __expf(mr1 - mn1);
            mr0 = mn0; mr1 = mn1;
            float s0 = 0.f, s1 = 0.f;
#pragma unroll
            for (int nt = 0; nt < 8; nt++) {
                const float p0 = __expf(sf[nt][0] - mn0);
                const float p1 = __expf(sf[nt][1] - mn0);
                const float p2 = __expf(sf[nt][2] - mn1);
                const float p3 = __expf(sf[nt][3] - mn1);
                s0 += p0 + p1; s1 += p2 + p3;
                const int col = nt * 8 + qd * 2;
                *(half2*)(sm + S_P + (slice + g) * PSTR + col * 2)     = __floats2half2_rn(p0, p1);
                *(half2*)(sm + S_P + (slice + g + 8) * PSTR + col * 2) = __floats2half2_rn(p2, p3);
            }
            s0 += __shfl_xor_sync(0xffffffffu, s0, 1);
            s0 += __shfl_xor_sync(0xffffffffu, s0, 2);
            s1 += __shfl_xor_sync(0xffffffffu, s1, 1);
            s1 += __shfl_xor_sync(0xffffffffu, s1, 2);
            l0 = l0 * cr0 + s0;
            l1 = l1 * cr1 + s1;
            if (qd == 0) { corr_s[slice + g] = cr0; corr_s[slice + g + 8] = cr1; }
        }
        __syncthreads();

        // ---- all warps: rescale O, then PV (fp16 mma) ----
        {
            const float c0 = corr_s[slice + g], c1 = corr_s[slice + g + 8];
#pragma unroll
            for (int j = 0; j < 16; j++) {
                of[j][0] *= c0; of[j][1] *= c0; of[j][2] *= c1; of[j][3] *= c1;
            }
        }
#pragma unroll
        for (int kc = 0; kc < 4; kc++) {
            uint32_t pa[4];
            ldsm4(pa, sb + S_P + (slice + (lane & 15)) * PSTR + kc * 32 + (lane >> 4) * 16);
            const int key = kc * 16 + (lane & 7) + ((lane >> 3) & 1) * 8;
#pragma unroll
            for (int jj = 0; jj < 8; jj++) {
                uint32_t vb[4];
                ldsm4t(vb, sb + S_V + key * QSTR + (doff + jj * 16) * 2 + ((lane >> 4) & 1) * 16);
                mma_f16(of[2 * jj],     pa, vb[0], vb[1]);
                mma_f16(of[2 * jj + 1], pa, vb[2], vb[3]);
            }
        }
    }

    // ---- normalize + store ----
    if (grp == 0 && qd == 0) {
        linv_s[slice + g]     = 1.f / l0;
        linv_s[slice + g + 8] = 1.f / l1;
    }
    __syncthreads();
    const float ia = linv_s[slice + g], ib = linv_s[slice + g + 8];
    const int row0 = m0 + slice + g;
#pragma unroll
    for (int nt = 0; nt < 16; nt++) {
        const int col = cb + doff + nt * 8 + qd * 2;
        *(float2*)&O[(size_t)row0 * EMBED + col] =
            make_float2(of[nt][0] * ia, of[nt][1] * ia);
        *(float2*)&O[(size_t)(row0 + 8) * EMBED + col] =
            make_float2(of[nt][2] * ib, of[nt][3] * ib);
    }
}

// ==============================================================================
// launch
// ==============================================================================
extern "C" void kernel_launch(void* const* d_in, const int* in_sizes, int n_in,
                              void* d_out, int out_size)
{
    (void)in_sizes; (void)n_in; (void)out_size;
    const float* X  = (const float*)d_in[0];
    const float* Wq = (const float*)d_in[1];
    const float* Wk = (const float*)d_in[2];
    const float* Wv = (const float*)d_in[3];
    const float* Wo = (const float*)d_in[4];
    float* out = (float*)d_out;

    float *q, *k, *v, *ao;
    __nv_bfloat16 *qhi, *qlo, *khi, *klo;
    __half* vh;
    cudaGetSymbolAddress((void**)&q,   g_q);
    cudaGetSymbolAddress((void**)&k,   g_k);
    cudaGetSymbolAddress((void**)&v,   g_v);
    cudaGetSymbolAddress((void**)&ao,  g_ao);
    cudaGetSymbolAddress((void**)&qhi, g_qhi);
    cudaGetSymbolAddress((void**)&qlo, g_qlo);
    cudaGetSymbolAddress((void**)&khi, g_khi);
    cudaGetSymbolAddress((void**)&klo, g_klo);
    cudaGetSymbolAddress((void**)&vh,  g_vh);

    cudaFuncSetAttribute(gemm_tf32,
                         cudaFuncAttributeMaxDynamicSharedMemorySize, GEMM_SMEM);
    cudaFuncSetAttribute(attn_mma,
                         cudaFuncAttributeMaxDynamicSharedMemorySize, ATT_SMEM);

    dim3 gg(4096 / BN, 4096 / BM);
    gemm_tf32<<<gg, 256, GEMM_SMEM>>>(X, Wq, q);
    gemm_tf32<<<gg, 256, GEMM_SMEM>>>(X, Wk, k);
    gemm_tf32<<<gg, 256, GEMM_SMEM>>>(X, Wv, v);

    prep_qkv<<<NELEM / 4 / 256, 256>>>(q, k, v, qhi, qlo, khi, klo, vh);

    dim3 ga(SEQ / 64, HEADS);
    attn_mma<<<ga, 256, ATT_SMEM>>>(qhi, qlo, khi, klo, vh, ao);

    gemm_tf32<<<gg, 256, GEMM_SMEM>>>(ao, Wo, out);
}

// round 5
// speedup vs baseline: 4.3209x; 1.3470x over previous
#include <cuda_runtime.h>
#include <cuda_bf16.h>
#include <cuda_fp16.h>
#include <math.h>
#include <stdint.h>

#define SEQ   4096
#define EMBED 4096
#define HEADS 16
#define HD    256
#define ROT   64
#define NELEM (SEQ * EMBED)

// ---------------- scratch (allocation-free rule: __device__ globals) ----------
__device__ float g_q [NELEM];
__device__ float g_k [NELEM];
__device__ float g_v [NELEM];
__device__ float g_ao[NELEM];
__device__ __nv_bfloat16 g_qhi[NELEM];
__device__ __nv_bfloat16 g_qlo[NELEM];
__device__ __nv_bfloat16 g_khi[NELEM];
__device__ __nv_bfloat16 g_klo[NELEM];
__device__ __half        g_vh [NELEM];
__device__ __half g_ah [NELEM];     // activation fp16 (X, later ao)
__device__ __half g_wqh[NELEM];
__device__ __half g_wkh[NELEM];
__device__ __half g_wvh[NELEM];
__device__ __half g_woh[NELEM];

// ==============================================================================
// helpers
// ==============================================================================
__device__ __forceinline__ void cp16(uint32_t dst, const void* src) {
    asm volatile("cp.async.cg.shared.global [%0], [%1], 16;" :: "r"(dst), "l"(src));
}

__device__ __forceinline__ void ldsm4(uint32_t* r, uint32_t a) {
    asm volatile("ldmatrix.sync.aligned.m8n8.x4.shared.b16 {%0,%1,%2,%3}, [%4];"
                 : "=r"(r[0]), "=r"(r[1]), "=r"(r[2]), "=r"(r[3]) : "r"(a));
}

__device__ __forceinline__ void ldsm4t(uint32_t* r, uint32_t a) {
    asm volatile("ldmatrix.sync.aligned.m8n8.x4.trans.shared.b16 {%0,%1,%2,%3}, [%4];"
                 : "=r"(r[0]), "=r"(r[1]), "=r"(r[2]), "=r"(r[3]) : "r"(a));
}

__device__ __forceinline__ void mma_bf16(float* c, const uint32_t* a,
                                         uint32_t b0, uint32_t b1) {
    asm volatile(
        "mma.sync.aligned.m16n8k16.row.col.f32.bf16.bf16.f32 "
        "{%0,%1,%2,%3}, {%4,%5,%6,%7}, {%8,%9}, {%0,%1,%2,%3};"
        : "+f"(c[0]), "+f"(c[1]), "+f"(c[2]), "+f"(c[3])
        : "r"(a[0]), "r"(a[1]), "r"(a[2]), "r"(a[3]), "r"(b0), "r"(b1));
}

__device__ __forceinline__ void mma_f16(float* c, const uint32_t* a,
                                        uint32_t b0, uint32_t b1) {
    asm volatile(
        "mma.sync.aligned.m16n8k16.row.col.f32.f16.f16.f32 "
        "{%0,%1,%2,%3}, {%4,%5,%6,%7}, {%8,%9}, {%0,%1,%2,%3};"
        : "+f"(c[0]), "+f"(c[1]), "+f"(c[2]), "+f"(c[3])
        : "r"(a[0]), "r"(a[1]), "r"(a[2]), "r"(a[3]), "r"(b0), "r"(b1));
}

// ==============================================================================
// fp32 -> fp16 conversion (DRAM-bound, ~20us per 64MB tensor)
// ==============================================================================
__global__ void cvt_f16(const float* __restrict__ x, __half* __restrict__ y)
{
    const int i = blockIdx.x * blockDim.x + threadIdx.x;
    float4 v = ((const float4*)x)[i];
    ((half2*)y)[2 * i]     = __floats2half2_rn(v.x, v.y);
    ((half2*)y)[2 * i + 1] = __floats2half2_rn(v.z, v.w);
}

// ==============================================================================
// fp16 tensor-core GEMM (NT): C[M,N] = A[M,K] * B[N,K]^T, fp32 accum.
// 128x128 block, BK=64, 8 warps (2x4), warp 64x32, m16n8k16 via ldmatrix.
// smem rows padded to 144B -> conflict-free ldmatrix. 2-stage cp.async.
// ==============================================================================
#define HSTR 144
#define HSTAGE (128 * HSTR * 2)          // A+B per stage = 36864 B
#define GEMM_SMEM (2 * HSTAGE)           // 73728 B

__global__ __launch_bounds__(256, 2)
void gemm_f16(const __half* __restrict__ A, const __half* __restrict__ B,
              float* __restrict__ C)
{
    extern __shared__ __align__(16) char smg[];
    const uint32_t sb = (uint32_t)__cvta_generic_to_shared(smg);

    const int tid  = threadIdx.x;
    const int lane = tid & 31;
    const int warp = tid >> 5;
    const int wm   = warp & 1;            // 64-row slab
    const int wn   = warp >> 1;           // 32-col slab
    const int m0   = blockIdx.y * 128;
    const int n0   = blockIdx.x * 128;

    const int ldr = tid >> 1;             // 0..127 row
    const int ldc = tid & 1;              // 2 x 32B halves... (see loader)

    float acc[4][4][4];
#pragma unroll
    for (int i = 0; i < 4; i++)
#pragma unroll
        for (int j = 0; j < 4; j++)
#pragma unroll
            for (int r = 0; r < 4; r++) acc[i][j][r] = 0.f;

    // loader: 128 rows x 128B per matrix per stage; 256 thr -> each thread
    // loads 4x16B for A and 4x16B for B (row = tid>>1, 64B half = tid&1).
    auto load_stage = [&](int stage, int kt) {
        const uint32_t st = sb + stage * HSTAGE;
#pragma unroll
        for (int c = 0; c < 4; c++) {
            const int cb = ldc * 64 + c * 16;
            cp16(st + ldr * HSTR + cb,
                 A + (size_t)(m0 + ldr) * 4096 + kt + cb / 2);
            cp16(st + 128 * HSTR + ldr * HSTR + cb,
                 B + (size_t)(n0 + ldr) * 4096 + kt + cb / 2);
        }
        asm volatile("cp.async.commit_group;");
    };

    load_stage(0, 0);

    const int NT = 4096 / 64;
    for (int t = 0; t < NT; t++) {
        const int cur = t & 1;
        if (t + 1 < NT) {
            load_stage(cur ^ 1, (t + 1) * 64);
            asm volatile("cp.async.wait_group 1;");
        } else {
            asm volatile("cp.async.wait_group 0;");
        }
        __syncthreads();

        const uint32_t ab = sb + cur * HSTAGE + (wm * 64) * HSTR;
        const uint32_t bb = sb + cur * HSTAGE + 128 * HSTR + (wn * 32) * HSTR;
        const uint32_t arow = (lane & 15) * HSTR + (lane >> 4) * 16;
        const uint32_t brow = ((lane & 7) + ((lane >> 4) & 1) * 8) * HSTR
                            + ((lane >> 3) & 1) * 16;

#pragma unroll
        for (int ks = 0; ks < 4; ks++) {
            const int kb = ks * 32;
            uint32_t af[4][4], bf[4][2];
#pragma unroll
            for (int mt = 0; mt < 4; mt++)
                ldsm4(af[mt], ab + mt * 16 * HSTR + arow + kb);
#pragma unroll
            for (int np = 0; np < 2; np++) {
                uint32_t b4[4];
                ldsm4(b4, bb + np * 16 * HSTR + brow + kb);
                bf[np * 2][0]     = b4[0]; bf[np * 2][1]     = b4[1];
                bf[np * 2 + 1][0] = b4[2]; bf[np * 2 + 1][1] = b4[3];
            }
#pragma unroll
            for (int mt = 0; mt < 4; mt++)
#pragma unroll
                for (int nt = 0; nt < 4; nt++)
                    mma_f16(acc[mt][nt], af[mt], bf[nt][0], bf[nt][1]);
        }
        __syncthreads();
    }

    // epilogue: c-fragment (g = lane>>2 row, qd = lane&3 col-pair)
    const int g  = lane >> 2;
    const int qd = lane & 3;
#pragma unroll
    for (int mt = 0; mt < 4; mt++) {
        const int r0 = m0 + wm * 64 + mt * 16 + g;
#pragma unroll
        for (int nt = 0; nt < 4; nt++) {
            const int col = n0 + wn * 32 + nt * 8 + qd * 2;
            *(float2*)&C[(size_t)r0 * 4096 + col] =
                make_float2(acc[mt][nt][0], acc[mt][nt][1]);
            *(float2*)&C[(size_t)(r0 + 8) * 4096 + col] =
                make_float2(acc[mt][nt][2], acc[mt][nt][3]);
        }
    }
}

// ==============================================================================
// prep: RoPE on q,k + emit bf16 hi/lo planes (q,k) and fp16 plane (v).
// ==============================================================================
__global__ void prep_qkv(const float* __restrict__ q, const float* __restrict__ k,
                         const float* __restrict__ v,
                         __nv_bfloat16* __restrict__ qhi, __nv_bfloat16* __restrict__ qlo,
                         __nv_bfloat16* __restrict__ khi, __nv_bfloat16* __restrict__ klo,
                         __half* __restrict__ vh)
{
    const int i = blockIdx.x * blockDim.x + threadIdx.x;
    const int e = i * 4;
    const int s = e >> 12;
    const int hd = e & 255;

    float4 qv = ((const float4*)q)[i];
    float4 kv = ((const float4*)k)[i];
    float4 vv = ((const float4*)v)[i];

    if (hd < ROT) {
        const int j0 = hd >> 1;
        float a0 = (float)s * powf(10000.f, -(float)j0 / 32.f);
        float a1 = (float)s * powf(10000.f, -(float)(j0 + 1) / 32.f);
        float s0, c0, s1, c1;
        sincosf(a0, &s0, &c0);
        sincosf(a1, &s1, &c1);
        float x, y;
        x = qv.x; y = qv.y; qv.x = x * c0 - y * s0; qv.y = y * c0 + x * s0;
        x = qv.z; y = qv.w; qv.z = x * c1 - y * s1; qv.w = y * c1 + x * s1;
        x = kv.x; y = kv.y; kv.x = x * c0 - y * s0; kv.y = y * c0 + x * s0;
        x = kv.z; y = kv.w; kv.z = x * c1 - y * s1; kv.w = y * c1 + x * s1;
    }

#define SPLIT2(vx, vy, hi2, lo2) {                                         \
        __nv_bfloat16 _h0 = __float2bfloat16_rn(vx);                       \
        __nv_bfloat16 _h1 = __float2bfloat16_rn(vy);                       \
        hi2 = __nv_bfloat162(_h0, _h1);                                    \
        lo2 = __nv_bfloat162(__float2bfloat16_rn((vx) - __bfloat162float(_h0)), \
                             __float2bfloat16_rn((vy) - __bfloat162float(_h1))); }

    __nv_bfloat162 h2, l2;
    SPLIT2(qv.x, qv.y, h2, l2);
    ((__nv_bfloat162*)qhi)[2 * i]     = h2; ((__nv_bfloat162*)qlo)[2 * i]     = l2;
    SPLIT2(qv.z, qv.w, h2, l2);
    ((__nv_bfloat162*)qhi)[2 * i + 1] = h2; ((__nv_bfloat162*)qlo)[2 * i + 1] = l2;
    SPLIT2(kv.x, kv.y, h2, l2);
    ((__nv_bfloat162*)khi)[2 * i]     = h2; ((__nv_bfloat162*)klo)[2 * i]     = l2;
    SPLIT2(kv.z, kv.w, h2, l2);
    ((__nv_bfloat162*)khi)[2 * i + 1] = h2; ((__nv_bfloat162*)klo)[2 * i + 1] = l2;

    ((half2*)vh)[2 * i]     = __floats2half2_rn(vv.x, vv.y);
    ((half2*)vh)[2 * i + 1] = __floats2half2_rn(vv.z, vv.w);
#undef SPLIT2
}

// ==============================================================================
// Tensor-core causal flash attention (unchanged from round 4 -- validated).
// ==============================================================================
#define QSTR 528
#define PSTR 144
#define S_QHI 0
#define S_QLO 33792
#define S_KHI 67584
#define S_KLO 101376
#define S_V   135168
#define S_SB  168960
#define S_P   186368
#define S_CORR 195584
#define S_LINV 195840
#define ATT_SMEM 196096

__global__ __launch_bounds__(256, 1)
void attn_mma(const __nv_bfloat16* __restrict__ Qhi, const __nv_bfloat16* __restrict__ Qlo,
              const __nv_bfloat16* __restrict__ Khi, const __nv_bfloat16* __restrict__ Klo,
              const __half* __restrict__ Vh, float* __restrict__ O)
{
    extern __shared__ __align__(16) char sm[];
    const uint32_t sb = (uint32_t)__cvta_generic_to_shared(sm);
    float* SBf    = (float*)(sm + S_SB);
    float* corr_s = (float*)(sm + S_CORR);
    float* linv_s = (float*)(sm + S_LINV);

    const int tid   = threadIdx.x;
    const int lane  = tid & 31;
    const int wid   = tid >> 5;
    const int grp   = wid >> 2;
    const int slice = (wid & 3) * 16;
    const int g     = lane >> 2;
    const int qd    = lane & 3;

    const int h    = blockIdx.y;
    const int m0   = ((int)gridDim.x - 1 - (int)blockIdx.x) * 64;
    const int cb   = h * HD;
    const int doff = grp * 128;

    for (int f = tid; f < 2048; f += 256) {
        const int r = f >> 5, c = f & 31;
        const size_t go = (size_t)(m0 + r) * EMBED + cb + c * 8;
        cp16(sb + S_QHI + r * QSTR + c * 16, Qhi + go);
        cp16(sb + S_QLO + r * QSTR + c * 16, Qlo + go);
    }

    float of[16][4];
#pragma unroll
    for (int j = 0; j < 16; j++)
#pragma unroll
        for (int r = 0; r < 4; r++) of[j][r] = 0.f;
    float mr0 = -1e30f, mr1 = -1e30f, l0 = 0.f, l1 = 0.f;

    const int ntl = m0 / 64 + 1;
    for (int t = 0; t < ntl; t++) {
        const int n0 = t * 64;
        __syncthreads();

        for (int f = tid; f < 2048; f += 256) {
            const int r = f >> 5, c = f & 31;
            const size_t go = (size_t)(n0 + r) * EMBED + cb + c * 8;
            cp16(sb + S_KHI + r * QSTR + c * 16, Khi + go);
            cp16(sb + S_KLO + r * QSTR + c * 16, Klo + go);
            cp16(sb + S_V   + r * QSTR + c * 16, Vh  + go);
        }
        asm volatile("cp.async.commit_group;");
        asm volatile("cp.async.wait_group 0;");
        __syncthreads();

        float sf[8][4];
#pragma unroll
        for (int nt = 0; nt < 8; nt++)
#pragma unroll
            for (int r = 0; r < 4; r++) sf[nt][r] = 0.f;

        const uint32_t qa = sb + S_QHI + (slice + (lane & 15)) * QSTR + (lane >> 4) * 16;
#pragma unroll
        for (int kc = 0; kc < 8; kc++) {
            const int dby = (doff + kc * 16) * 2;
            uint32_t qh[4], ql[4];
            ldsm4(qh, qa + dby);
            ldsm4(ql, qa + dby + (S_QLO - S_QHI));
#pragma unroll
            for (int kg = 0; kg < 4; kg++) {
                const int key = kg * 16 + (lane & 7) + ((lane >> 4) & 1) * 8;
                const uint32_t ba = sb + S_KHI + key * QSTR + dby + ((lane >> 3) & 1) * 16;
                uint32_t kh[4], kl[4];
                ldsm4(kh, ba);
                ldsm4(kl, ba + (S_KLO - S_KHI));
                mma_bf16(sf[2 * kg],     qh, kh[0], kh[1]);
                mma_bf16(sf[2 * kg],     qh, kl[0], kl[1]);
                mma_bf16(sf[2 * kg],     ql, kh[0], kh[1]);
                mma_bf16(sf[2 * kg + 1], qh, kh[2], kh[3]);
                mma_bf16(sf[2 * kg + 1], qh, kl[2], kl[3]);
                mma_bf16(sf[2 * kg + 1], ql, kh[2], kh[3]);
            }
        }

        if (grp == 1) {
#pragma unroll
            for (int nt = 0; nt < 8; nt++) {
                const int col = nt * 8 + qd * 2;
                *(float2*)&SBf[(slice + g) * 68 + col]     = make_float2(sf[nt][0], sf[nt][1]);
                *(float2*)&SBf[(slice + g + 8) * 68 + col] = make_float2(sf[nt][2], sf[nt][3]);
            }
        }
        __syncthreads();

        if (grp == 0) {
            const int row0 = m0 + slice + g, row1 = row0 + 8;
            float px0 = -1e30f, px1 = -1e30f;
#pragma unroll
            for (int nt = 0; nt < 8; nt++) {
                const int col = nt * 8 + qd * 2;
                const float2 b0 = *(float2*)&SBf[(slice + g) * 68 + col];
                const float2 b1 = *(float2*)&SBf[(slice + g + 8) * 68 + col];
                const int cg = n0 + col;
                sf[nt][0] = (cg     <= row0) ? (sf[nt][0] + b0.x) * 0.0625f : -1e30f;
                sf[nt][1] = (cg + 1 <= row0) ? (sf[nt][1] + b0.y) * 0.0625f : -1e30f;
                sf[nt][2] = (cg     <= row1) ? (sf[nt][2] + b1.x) * 0.0625f : -1e30f;
                sf[nt][3] = (cg + 1 <= row1) ? (sf[nt][3] + b1.y) * 0.0625f : -1e30f;
                px0 = fmaxf(px0, fmaxf(sf[nt][0], sf[nt][1]));
                px1 = fmaxf(px1, fmaxf(sf[nt][2], sf[nt][3]));
            }
            px0 = fmaxf(px0, __shfl_xor_sync(0xffffffffu, px0, 1));
            px0 = fmaxf(px0, __shfl_xor_sync(0xffffffffu, px0, 2));
            px1 = fmaxf(px1, __shfl_xor_sync(0xffffffffu, px1, 1));
            px1 = fmaxf(px1, __shfl_xor_sync(0xffffffffu, px1, 2));
            const float mn0 = fmaxf(mr0, px0), mn1 = fmaxf(mr1, px1);
            const float cr0 = __expf(mr0 - mn0), cr1 = __expf(mr1 - mn1);
            mr0 = mn0; mr1 = mn1;
            float s0 = 0.f, s1 = 0.f;
#pragma unroll
            for (int nt = 0; nt < 8; nt++) {
                const float p0 = __expf(sf[nt][0] - mn0);
                const float p1 = __expf(sf[nt][1] - mn0);
                const float p2 = __expf(sf[nt][2] - mn1);
                const float p3 = __expf(sf[nt][3] - mn1);
                s0 += p0 + p1; s1 += p2 + p3;
                const int col = nt * 8 + qd * 2;
                *(half2*)(sm + S_P + (slice + g) * PSTR + col * 2)     = __floats2half2_rn(p0, p1);
                *(half2*)(sm + S_P + (slice + g + 8) * PSTR + col * 2) = __floats2half2_rn(p2, p3);
            }
            s0 += __shfl_xor_sync(0xffffffffu, s0, 1);
            s0 += __shfl_xor_sync(0xffffffffu, s0, 2);
            s1 += __shfl_xor_sync(0xffffffffu, s1, 1);
            s1 += __shfl_xor_sync(0xffffffffu, s1, 2);
            l0 = l0 * cr0 + s0;
            l1 = l1 * cr1 + s1;
            if (qd == 0) { corr_s[slice + g] = cr0; corr_s[slice + g + 8] = cr1; }
        }
        __syncthreads();

        {
            const float c0 = corr_s[slice + g], c1 = corr_s[slice + g + 8];
#pragma unroll
            for (int j = 0; j < 16; j++) {
                of[j][0] *= c0; of[j][1] *= c0; of[j][2] *= c1; of[j][3] *= c1;
            }
        }
#pragma unroll
        for (int kc = 0; kc < 4; kc++) {
            uint32_t pa[4];
            ldsm4(pa, sb + S_P + (slice + (lane & 15)) * PSTR + kc * 32 + (lane >> 4) * 16);
            const int key = kc * 16 + (lane & 7) + ((lane >> 3) & 1) * 8;
#pragma unroll
            for (int jj = 0; jj < 8; jj++) {
                uint32_t vb[4];
                ldsm4t(vb, sb + S_V + key * QSTR + (doff + jj * 16) * 2 + ((lane >> 4) & 1) * 16);
                mma_f16(of[2 * jj],     pa, vb[0], vb[1]);
                mma_f16(of[2 * jj + 1], pa, vb[2], vb[3]);
            }
        }
    }

    if (grp == 0 && qd == 0) {
        linv_s[slice + g]     = 1.f / l0;
        linv_s[slice + g + 8] = 1.f / l1;
    }
    __syncthreads();
    const float ia = linv_s[slice + g], ib = linv_s[slice + g + 8];
    const int row0 = m0 + slice + g;
#pragma unroll
    for (int nt = 0; nt < 16; nt++) {
        const int col = cb + doff + nt * 8 + qd * 2;
        *(float2*)&O[(size_t)row0 * EMBED + col] =
            make_float2(of[nt][0] * ia, of[nt][1] * ia);
        *(float2*)&O[(size_t)(row0 + 8) * EMBED + col] =
            make_float2(of[nt][2] * ib, of[nt][3] * ib);
    }
}

// ==============================================================================
// launch
// ==============================================================================
extern "C" void kernel_launch(void* const* d_in, const int* in_sizes, int n_in,
                              void* d_out, int out_size)
{
    (void)in_sizes; (void)n_in; (void)out_size;
    const float* X  = (const float*)d_in[0];
    const float* Wq = (const float*)d_in[1];
    const float* Wk = (const float*)d_in[2];
    const float* Wv = (const float*)d_in[3];
    const float* Wo = (const float*)d_in[4];
    float* out = (float*)d_out;

    float *q, *k, *v, *ao;
    __nv_bfloat16 *qhi, *qlo, *khi, *klo;
    __half *vh, *ah, *wqh, *wkh, *wvh, *woh;
    cudaGetSymbolAddress((void**)&q,   g_q);
    cudaGetSymbolAddress((void**)&k,   g_k);
    cudaGetSymbolAddress((void**)&v,   g_v);
    cudaGetSymbolAddress((void**)&ao,  g_ao);
    cudaGetSymbolAddress((void**)&qhi, g_qhi);
    cudaGetSymbolAddress((void**)&qlo, g_qlo);
    cudaGetSymbolAddress((void**)&khi, g_khi);
    cudaGetSymbolAddress((void**)&klo, g_klo);
    cudaGetSymbolAddress((void**)&vh,  g_vh);
    cudaGetSymbolAddress((void**)&ah,  g_ah);
    cudaGetSymbolAddress((void**)&wqh, g_wqh);
    cudaGetSymbolAddress((void**)&wkh, g_wkh);
    cudaGetSymbolAddress((void**)&wvh, g_wvh);
    cudaGetSymbolAddress((void**)&woh, g_woh);

    cudaFuncSetAttribute(gemm_f16,
                         cudaFuncAttributeMaxDynamicSharedMemorySize, GEMM_SMEM);
    cudaFuncSetAttribute(attn_mma,
                         cudaFuncAttributeMaxDynamicSharedMemorySize, ATT_SMEM);

    const int CVB = NELEM / 4 / 256;
    cvt_f16<<<CVB, 256>>>(X,  ah);
    cvt_f16<<<CVB, 256>>>(Wq, wqh);
    cvt_f16<<<CVB, 256>>>(Wk, wkh);
    cvt_f16<<<CVB, 256>>>(Wv, wvh);
    cvt_f16<<<CVB, 256>>>(Wo, woh);

    dim3 gg(32, 32);
    gemm_f16<<<gg, 256, GEMM_SMEM>>>(ah, wqh, q);
    gemm_f16<<<gg, 256, GEMM_SMEM>>>(ah, wkh, k);
    gemm_f16<<<gg, 256, GEMM_SMEM>>>(ah, wvh, v);

    prep_qkv<<<NELEM / 4 / 256, 256>>>(q, k, v, qhi, qlo, khi, klo, vh);

    dim3 ga(SEQ / 64, HEADS);
    attn_mma<<<ga, 256, ATT_SMEM>>>(qhi, qlo, khi, klo, vh, ao);

    cvt_f16<<<CVB, 256>>>(ao, ah);
    gemm_f16<<<gg, 256, GEMM_SMEM>>>(ah, woh, out);
}

// round 6
// speedup vs baseline: 4.4503x; 1.0299x over previous
#include <cuda_runtime.h>
#include <cuda_bf16.h>
#include <cuda_fp16.h>
#include <math.h>
#include <stdint.h>

#define SEQ   4096
#define EMBED 4096
#define HEADS 16
#define HD    256
#define ROT   64
#define NELEM (SEQ * EMBED)

// ---------------- scratch (allocation-free rule: __device__ globals) ----------
__device__ float g_q [NELEM];
__device__ float g_k [NELEM];
__device__ float g_v [NELEM];
__device__ float g_ao[NELEM];
__device__ __nv_bfloat16 g_qhi[NELEM];
__device__ __nv_bfloat16 g_qlo[NELEM];
__device__ __nv_bfloat16 g_khi[NELEM];
__device__ __nv_bfloat16 g_klo[NELEM];
__device__ __half        g_vh [NELEM];
__device__ __half g_ah [NELEM];
__device__ __half g_wqh[NELEM];
__device__ __half g_wkh[NELEM];
__device__ __half g_wvh[NELEM];
__device__ __half g_woh[NELEM];

// ==============================================================================
// helpers
// ==============================================================================
__device__ __forceinline__ void cp16(uint32_t dst, const void* src) {
    asm volatile("cp.async.cg.shared.global [%0], [%1], 16;" :: "r"(dst), "l"(src));
}

__device__ __forceinline__ void ldsm4(uint32_t* r, uint32_t a) {
    asm volatile("ldmatrix.sync.aligned.m8n8.x4.shared.b16 {%0,%1,%2,%3}, [%4];"
                 : "=r"(r[0]), "=r"(r[1]), "=r"(r[2]), "=r"(r[3]) : "r"(a));
}

__device__ __forceinline__ void ldsm4t(uint32_t* r, uint32_t a) {
    asm volatile("ldmatrix.sync.aligned.m8n8.x4.trans.shared.b16 {%0,%1,%2,%3}, [%4];"
                 : "=r"(r[0]), "=r"(r[1]), "=r"(r[2]), "=r"(r[3]) : "r"(a));
}

__device__ __forceinline__ void mma_bf16(float* c, const uint32_t* a,
                                         uint32_t b0, uint32_t b1) {
    asm volatile(
        "mma.sync.aligned.m16n8k16.row.col.f32.bf16.bf16.f32 "
        "{%0,%1,%2,%3}, {%4,%5,%6,%7}, {%8,%9}, {%0,%1,%2,%3};"
        : "+f"(c[0]), "+f"(c[1]), "+f"(c[2]), "+f"(c[3])
        : "r"(a[0]), "r"(a[1]), "r"(a[2]), "r"(a[3]), "r"(b0), "r"(b1));
}

__device__ __forceinline__ void mma_f16(float* c, const uint32_t* a,
                                        uint32_t b0, uint32_t b1) {
    asm volatile(
        "mma.sync.aligned.m16n8k16.row.col.f32.f16.f16.f32 "
        "{%0,%1,%2,%3}, {%4,%5,%6,%7}, {%8,%9}, {%0,%1,%2,%3};"
        : "+f"(c[0]), "+f"(c[1]), "+f"(c[2]), "+f"(c[3])
        : "r"(a[0]), "r"(a[1]), "r"(a[2]), "r"(a[3]), "r"(b0), "r"(b1));
}

// ==============================================================================
// fp32 -> fp16 conversion
// ==============================================================================
__global__ void cvt_f16(const float* __restrict__ x, __half* __restrict__ y)
{
    const int i = blockIdx.x * blockDim.x + threadIdx.x;
    float4 v = ((const float4*)x)[i];
    ((half2*)y)[2 * i]     = __floats2half2_rn(v.x, v.y);
    ((half2*)y)[2 * i + 1] = __floats2half2_rn(v.z, v.w);
}

// ==============================================================================
// fp16 tensor-core GEMM (NT): C[M,N] = A[M,K] * B[N,K]^T, fp32 accum.
// 128x256 block, BK=32, 8 warps (2x4) each 64x64, 4-stage cp.async pipeline.
// smem rows padded to 80B (16B-aligned, 80r mod 128 covers all 8 bank groups
// -> conflict-free ldmatrix).
// ==============================================================================
#define HSTR  80
#define SOFFB (128 * HSTR)                  // B offset within stage (10240)
#define SSTG  (128 * HSTR + 256 * HSTR)     // 30720 B per stage
#define GEMM_SMEM (4 * SSTG)                // 122880 B

__global__ __launch_bounds__(256, 1)
void gemm_f16(const __half* __restrict__ A, const __half* __restrict__ B,
              float* __restrict__ C)
{
    extern __shared__ __align__(16) char smg[];
    const uint32_t sb = (uint32_t)__cvta_generic_to_shared(smg);

    const int tid  = threadIdx.x;
    const int lane = tid & 31;
    const int warp = tid >> 5;
    const int wm   = warp & 1;              // 64-row slab
    const int wn   = warp >> 1;             // 64-col slab
    const int m0   = blockIdx.y * 128;
    const int n0   = blockIdx.x * 256;

    float acc[4][8][4];
#pragma unroll
    for (int i = 0; i < 4; i++)
#pragma unroll
        for (int j = 0; j < 8; j++)
#pragma unroll
            for (int r = 0; r < 4; r++) acc[i][j][r] = 0.f;

    // loader: A 128 rows x 64B (512 chunks), B 256 rows x 64B (1024 chunks)
    auto load_stage = [&](int stage, int kt) {
        const uint32_t st = sb + stage * SSTG;
#pragma unroll
        for (int i = 0; i < 2; i++) {
            const int f = tid + i * 256;
            const int r = f >> 2, c = f & 3;
            cp16(st + r * HSTR + c * 16,
                 A + (size_t)(m0 + r) * 4096 + kt + c * 8);
        }
#pragma unroll
        for (int i = 0; i < 4; i++) {
            const int f = tid + i * 256;
            const int r = f >> 2, c = f & 3;
            cp16(st + SOFFB + r * HSTR + c * 16,
                 B + (size_t)(n0 + r) * 4096 + kt + c * 8);
        }
        asm volatile("cp.async.commit_group;");
    };

    load_stage(0, 0);
    load_stage(1, 32);
    load_stage(2, 64);

    const uint32_t arow = (lane & 15) * HSTR + (lane >> 4) * 16;
    const uint32_t brow = ((lane & 7) + ((lane >> 4) & 1) * 8) * HSTR
                        + ((lane >> 3) & 1) * 16;
    const int NT = 4096 / 32;   // 128

    for (int t = 0; t < NT; t++) {
        if (t <= NT - 3)      asm volatile("cp.async.wait_group 2;");
        else if (t == NT - 2) asm volatile("cp.async.wait_group 1;");
        else                  asm volatile("cp.async.wait_group 0;");
        __syncthreads();

        if (t + 3 < NT) load_stage((t + 3) & 3, (t + 3) * 32);

        const uint32_t ab = sb + (t & 3) * SSTG + (wm * 64) * HSTR;
        const uint32_t bb = sb + (t & 3) * SSTG + SOFFB + (wn * 64) * HSTR;

#pragma unroll
        for (int ks = 0; ks < 2; ks++) {
            const int kb = ks * 32;
            uint32_t af[4][4];
#pragma unroll
            for (int mt = 0; mt < 4; mt++)
                ldsm4(af[mt], ab + mt * 16 * HSTR + arow + kb);
#pragma unroll
            for (int np = 0; np < 4; np++) {
                uint32_t b4[4];
                ldsm4(b4, bb + np * 16 * HSTR + brow + kb);
#pragma unroll
                for (int mt = 0; mt < 4; mt++) {
                    mma_f16(acc[mt][np * 2],     af[mt], b4[0], b4[1]);
                    mma_f16(acc[mt][np * 2 + 1], af[mt], b4[2], b4[3]);
                }
            }
        }
        __syncthreads();
    }

    // epilogue
    const int g  = lane >> 2;
    const int qd = lane & 3;
#pragma unroll
    for (int mt = 0; mt < 4; mt++) {
        const int r0 = m0 + wm * 64 + mt * 16 + g;
#pragma unroll
        for (int nt = 0; nt < 8; nt++) {
            const int col = n0 + wn * 64 + nt * 8 + qd * 2;
            *(float2*)&C[(size_t)r0 * 4096 + col] =
                make_float2(acc[mt][nt][0], acc[mt][nt][1]);
            *(float2*)&C[(size_t)(r0 + 8) * 4096 + col] =
                make_float2(acc[mt][nt][2], acc[mt][nt][3]);
        }
    }
}

// ==============================================================================
// prep: RoPE on q,k + emit bf16 hi/lo planes (q,k) and fp16 plane (v).
// ==============================================================================
__global__ void prep_qkv(const float* __restrict__ q, const float* __restrict__ k,
                         const float* __restrict__ v,
                         __nv_bfloat16* __restrict__ qhi, __nv_bfloat16* __restrict__ qlo,
                         __nv_bfloat16* __restrict__ khi, __nv_bfloat16* __restrict__ klo,
                         __half* __restrict__ vh)
{
    const int i = blockIdx.x * blockDim.x + threadIdx.x;
    const int e = i * 4;
    const int s = e >> 12;
    const int hd = e & 255;

    float4 qv = ((const float4*)q)[i];
    float4 kv = ((const float4*)k)[i];
    float4 vv = ((const float4*)v)[i];

    if (hd < ROT) {
        const int j0 = hd >> 1;
        float a0 = (float)s * powf(10000.f, -(float)j0 / 32.f);
        float a1 = (float)s * powf(10000.f, -(float)(j0 + 1) / 32.f);
        float s0, c0, s1, c1;
        sincosf(a0, &s0, &c0);
        sincosf(a1, &s1, &c1);
        float x, y;
        x = qv.x; y = qv.y; qv.x = x * c0 - y * s0; qv.y = y * c0 + x * s0;
        x = qv.z; y = qv.w; qv.z = x * c1 - y * s1; qv.w = y * c1 + x * s1;
        x = kv.x; y = kv.y; kv.x = x * c0 - y * s0; kv.y = y * c0 + x * s0;
        x = kv.z; y = kv.w; kv.z = x * c1 - y * s1; kv.w = y * c1 + x * s1;
    }

#define SPLIT2(vx, vy, hi2, lo2) {                                         \
        __nv_bfloat16 _h0 = __float2bfloat16_rn(vx);                       \
        __nv_bfloat16 _h1 = __float2bfloat16_rn(vy);                       \
        hi2 = __nv_bfloat162(_h0, _h1);                                    \
        lo2 = __nv_bfloat162(__float2bfloat16_rn((vx) - __bfloat162float(_h0)), \
                             __float2bfloat16_rn((vy) - __bfloat162float(_h1))); }

    __nv_bfloat162 h2, l2;
    SPLIT2(qv.x, qv.y, h2, l2);
    ((__nv_bfloat162*)qhi)[2 * i]     = h2; ((__nv_bfloat162*)qlo)[2 * i]     = l2;
    SPLIT2(qv.z, qv.w, h2, l2);
    ((__nv_bfloat162*)qhi)[2 * i + 1] = h2; ((__nv_bfloat162*)qlo)[2 * i + 1] = l2;
    SPLIT2(kv.x, kv.y, h2, l2);
    ((__nv_bfloat162*)khi)[2 * i]     = h2; ((__nv_bfloat162*)klo)[2 * i]     = l2;
    SPLIT2(kv.z, kv.w, h2, l2);
    ((__nv_bfloat162*)khi)[2 * i + 1] = h2; ((__nv_bfloat162*)klo)[2 * i + 1] = l2;

    ((half2*)vh)[2 * i]     = __floats2half2_rn(vv.x, vv.y);
    ((half2*)vh)[2 * i + 1] = __floats2half2_rn(vv.z, vv.w);
#undef SPLIT2
}

// ==============================================================================
// Tensor-core causal flash attention (validated round 4/5; unchanged).
// ==============================================================================
#define QSTR 528
#define PSTR 144
#define S_QHI 0
#define S_QLO 33792
#define S_KHI 67584
#define S_KLO 101376
#define S_V   135168
#define S_SB  168960
#define S_P   186368
#define S_CORR 195584
#define S_LINV 195840
#define ATT_SMEM 196096

__global__ __launch_bounds__(256, 1)
void attn_mma(const __nv_bfloat16* __restrict__ Qhi, const __nv_bfloat16* __restrict__ Qlo,
              const __nv_bfloat16* __restrict__ Khi, const __nv_bfloat16* __restrict__ Klo,
              const __half* __restrict__ Vh, float* __restrict__ O)
{
    extern __shared__ __align__(16) char sm[];
    const uint32_t sb = (uint32_t)__cvta_generic_to_shared(sm);
    float* SBf    = (float*)(sm + S_SB);
    float* corr_s = (float*)(sm + S_CORR);
    float* linv_s = (float*)(sm + S_LINV);

    const int tid   = threadIdx.x;
    const int lane  = tid & 31;
    const int wid   = tid >> 5;
    const int grp   = wid >> 2;
    const int slice = (wid & 3) * 16;
    const int g     = lane >> 2;
    const int qd    = lane & 3;

    const int h    = blockIdx.y;
    const int m0   = ((int)gridDim.x - 1 - (int)blockIdx.x) * 64;
    const int cb   = h * HD;
    const int doff = grp * 128;

    for (int f = tid; f < 2048; f += 256) {
        const int r = f >> 5, c = f & 31;
        const size_t go = (size_t)(m0 + r) * EMBED + cb + c * 8;
        cp16(sb + S_QHI + r * QSTR + c * 16, Qhi + go);
        cp16(sb + S_QLO + r * QSTR + c * 16, Qlo + go);
    }

    float of[16][4];
#pragma unroll
    for (int j = 0; j < 16; j++)
#pragma unroll
        for (int r = 0; r < 4; r++) of[j][r] = 0.f;
    float mr0 = -1e30f, mr1 = -1e30f, l0 = 0.f, l1 = 0.f;

    const int ntl = m0 / 64 + 1;
    for (int t = 0; t < ntl; t++) {
        const int n0 = t * 64;
        __syncthreads();

        for (int f = tid; f < 2048; f += 256) {
            const int r = f >> 5, c = f & 31;
            const size_t go = (size_t)(n0 + r) * EMBED + cb + c * 8;
            cp16(sb + S_KHI + r * QSTR + c * 16, Khi + go);
            cp16(sb + S_KLO + r * QSTR + c * 16, Klo + go);
            cp16(sb + S_V   + r * QSTR + c * 16, Vh  + go);
        }
        asm volatile("cp.async.commit_group;");
        asm volatile("cp.async.wait_group 0;");
        __syncthreads();

        float sf[8][4];
#pragma unroll
        for (int nt = 0; nt < 8; nt++)
#pragma unroll
            for (int r = 0; r < 4; r++) sf[nt][r] = 0.f;

        const uint32_t qa = sb + S_QHI + (slice + (lane & 15)) * QSTR + (lane >> 4) * 16;
#pragma unroll
        for (int kc = 0; kc < 8; kc++) {
            const int dby = (doff + kc * 16) * 2;
            uint32_t qh[4], ql[4];
            ldsm4(qh, qa + dby);
            ldsm4(ql, qa + dby + (S_QLO - S_QHI));
#pragma unroll
            for (int kg = 0; kg < 4; kg++) {
                const int key = kg * 16 + (lane & 7) + ((lane >> 4) & 1) * 8;
                const uint32_t ba = sb + S_KHI + key * QSTR + dby + ((lane >> 3) & 1) * 16;
                uint32_t kh[4], kl[4];
                ldsm4(kh, ba);
                ldsm4(kl, ba + (S_KLO - S_KHI));
                mma_bf16(sf[2 * kg],     qh, kh[0], kh[1]);
                mma_bf16(sf[2 * kg],     qh, kl[0], kl[1]);
                mma_bf16(sf[2 * kg],     ql, kh[0], kh[1]);
                mma_bf16(sf[2 * kg + 1], qh, kh[2], kh[3]);
                mma_bf16(sf[2 * kg + 1], qh, kl[2], kl[3]);
                mma_bf16(sf[2 * kg + 1], ql, kh[2], kh[3]);
            }
        }

        if (grp == 1) {
#pragma unroll
            for (int nt = 0; nt < 8; nt++) {
                const int col = nt * 8 + qd * 2;
                *(float2*)&SBf[(slice + g) * 68 + col]     = make_float2(sf[nt][0], sf[nt][1]);
                *(float2*)&SBf[(slice + g + 8) * 68 + col] = make_float2(sf[nt][2], sf[nt][3]);
            }
        }
        __syncthreads();

        if (grp == 0) {
            const int row0 = m0 + slice + g, row1 = row0 + 8;
            float px0 = -1e30f, px1 = -1e30f;
#pragma unroll
            for (int nt = 0; nt < 8; nt++) {
                const int col = nt * 8 + qd * 2;
                const float2 b0 = *(float2*)&SBf[(slice + g) * 68 + col];
                const float2 b1 = *(float2*)&SBf[(slice + g + 8) * 68 + col];
                const int cg = n0 + col;
                sf[nt][0] = (cg     <= row0) ? (sf[nt][0] + b0.x) * 0.0625f : -1e30f;
                sf[nt][1] = (cg + 1 <= row0) ? (sf[nt][1] + b0.y) * 0.0625f : -1e30f;
                sf[nt][2] = (cg     <= row1) ? (sf[nt][2] + b1.x) * 0.0625f : -1e30f;
                sf[nt][3] = (cg + 1 <= row1) ? (sf[nt][3] + b1.y) * 0.0625f : -1e30f;
                px0 = fmaxf(px0, fmaxf(sf[nt][0], sf[nt][1]));
                px1 = fmaxf(px1, fmaxf(sf[nt][2], sf[nt][3]));
            }
            px0 = fmaxf(px0, __shfl_xor_sync(0xffffffffu, px0, 1));
            px0 = fmaxf(px0, __shfl_xor_sync(0xffffffffu, px0, 2));
            px1 = fmaxf(px1, __shfl_xor_sync(0xffffffffu, px1, 1));
            px1 = fmaxf(px1, __shfl_xor_sync(0xffffffffu, px1, 2));
            const float mn0 = fmaxf(mr0, px0), mn1 = fmaxf(mr1, px1);
            const float cr0 = __expf(mr0 - mn0), cr1 = __expf(mr1 - mn1);
            mr0 = mn0; mr1 = mn1;
            float s0 = 0.f, s1 = 0.f;
#pragma unroll
            for (int nt = 0; nt < 8; nt++) {
                const float p0 = __expf(sf[nt][0] - mn0);
                const float p1 = __expf(sf[nt][1] - mn0);
                const float p2 = __expf(sf[nt][2] - mn1);
                const float p3 = __expf(sf[nt][3] - mn1);
                s0 += p0 + p1; s1 += p2 + p3;
                const int col = nt * 8 + qd * 2;
                *(half2*)(sm + S_P + (slice + g) * PSTR + col * 2)     = __floats2half2_rn(p0, p1);
                *(half2*)(sm + S_P + (slice + g + 8) * PSTR + col * 2) = __floats2half2_rn(p2, p3);
            }
            s0 += __shfl_xor_sync(0xffffffffu, s0, 1);
            s0 += __shfl_xor_sync(0xffffffffu, s0, 2);
            s1 += __shfl_xor_sync(0xffffffffu, s1, 1);
            s1 += __shfl_xor_sync(0xffffffffu, s1, 2);
            l0 = l0 * cr0 + s0;
            l1 = l1 * cr1 + s1;
            if (qd == 0) { corr_s[slice + g] = cr0; corr_s[slice + g + 8] = cr1; }
        }
        __syncthreads();

        {
            const float c0 = corr_s[slice + g], c1 = corr_s[slice + g + 8];
#pragma unroll
            for (int j = 0; j < 16; j++) {
                of[j][0] *= c0; of[j][1] *= c0; of[j][2] *= c1; of[j][3] *= c1;
            }
        }
#pragma unroll
        for (int kc = 0; kc < 4; kc++) {
            uint32_t pa[4];
            ldsm4(pa, sb + S_P + (slice + (lane & 15)) * PSTR + kc * 32 + (lane >> 4) * 16);
            const int key = kc * 16 + (lane & 7) + ((lane >> 3) & 1) * 8;
#pragma unroll
            for (int jj = 0; jj < 8; jj++) {
                uint32_t vb[4];
                ldsm4t(vb, sb + S_V + key * QSTR + (doff + jj * 16) * 2 + ((lane >> 4) & 1) * 16);
                mma_f16(of[2 * jj],     pa, vb[0], vb[1]);
                mma_f16(of[2 * jj + 1], pa, vb[2], vb[3]);
            }
        }
    }

    if (grp == 0 && qd == 0) {
        linv_s[slice + g]     = 1.f / l0;
        linv_s[slice + g + 8] = 1.f / l1;
    }
    __syncthreads();
    const float ia = linv_s[slice + g], ib = linv_s[slice + g + 8];
    const int row0 = m0 + slice + g;
#pragma unroll
    for (int nt = 0; nt < 16; nt++) {
        const int col = cb + doff + nt * 8 + qd * 2;
        *(float2*)&O[(size_t)row0 * EMBED + col] =
            make_float2(of[nt][0] * ia, of[nt][1] * ia);
        *(float2*)&O[(size_t)(row0 + 8) * EMBED + col] =
            make_float2(of[nt][2] * ib, of[nt][3] * ib);
    }
}

// ==============================================================================
// launch
// ==============================================================================
extern "C" void kernel_launch(void* const* d_in, const int* in_sizes, int n_in,
                              void* d_out, int out_size)
{
    (void)in_sizes; (void)n_in; (void)out_size;
    const float* X  = (const float*)d_in[0];
    const float* Wq = (const float*)d_in[1];
    const float* Wk = (const float*)d_in[2];
    const float* Wv = (const float*)d_in[3];
    const float* Wo = (const float*)d_in[4];
    float* out = (float*)d_out;

    float *q, *k, *v, *ao;
    __nv_bfloat16 *qhi, *qlo, *khi, *klo;
    __half *vh, *ah, *wqh, *wkh, *wvh, *woh;
    cudaGetSymbolAddress((void**)&q,   g_q);
    cudaGetSymbolAddress((void**)&k,   g_k);
    cudaGetSymbolAddress((void**)&v,   g_v);
    cudaGetSymbolAddress((void**)&ao,  g_ao);
    cudaGetSymbolAddress((void**)&qhi, g_qhi);
    cudaGetSymbolAddress((void**)&qlo, g_qlo);
    cudaGetSymbolAddress((void**)&khi, g_khi);
    cudaGetSymbolAddress((void**)&klo, g_klo);
    cudaGetSymbolAddress((void**)&vh,  g_vh);
    cudaGetSymbolAddress((void**)&ah,  g_ah);
    cudaGetSymbolAddress((void**)&wqh, g_wqh);
    cudaGetSymbolAddress((void**)&wkh, g_wkh);
    cudaGetSymbolAddress((void**)&wvh, g_wvh);
    cudaGetSymbolAddress((void**)&woh, g_woh);

    cudaFuncSetAttribute(gemm_f16,
                         cudaFuncAttributeMaxDynamicSharedMemorySize, GEMM_SMEM);
    cudaFuncSetAttribute(attn_mma,
                         cudaFuncAttributeMaxDynamicSharedMemorySize, ATT_SMEM);

    const int CVB = NELEM / 4 / 256;
    cvt_f16<<<CVB, 256>>>(X,  ah);
    cvt_f16<<<CVB, 256>>>(Wq, wqh);
    cvt_f16<<<CVB, 256>>>(Wk, wkh);
    cvt_f16<<<CVB, 256>>>(Wv, wvh);
    cvt_f16<<<CVB, 256>>>(Wo, woh);

    dim3 gg(4096 / 256, 4096 / 128);    // (16, 32)
    gemm_f16<<<gg, 256, GEMM_SMEM>>>(ah, wqh, q);
    gemm_f16<<<gg, 256, GEMM_SMEM>>>(ah, wkh, k);
    gemm_f16<<<gg, 256, GEMM_SMEM>>>(ah, wvh, v);

    prep_qkv<<<NELEM / 4 / 256, 256>>>(q, k, v, qhi, qlo, khi, klo, vh);

    dim3 ga(SEQ / 64, HEADS);
    attn_mma<<<ga, 256, ATT_SMEM>>>(qhi, qlo, khi, klo, vh, ao);

    cvt_f16<<<CVB, 256>>>(ao, ah);
    gemm_f16<<<gg, 256, GEMM_SMEM>>>(ah, woh, out);
}

// round 7
// speedup vs baseline: 5.1226x; 1.1511x over previous
#include <cuda_runtime.h>
#include <cuda_bf16.h>
#include <cuda_fp16.h>
#include <math.h>
#include <stdint.h>

#define SEQ   4096
#define EMBED 4096
#define HEADS 16
#define HD    256
#define ROT   64
#define NELEM (SEQ * EMBED)

// ---------------- scratch (allocation-free rule: __device__ globals) ----------
__device__ float g_q [NELEM];
__device__ float g_k [NELEM];
__device__ float g_v [NELEM];
__device__ float g_ao[NELEM];
__device__ __nv_bfloat16 g_qhi[NELEM];
__device__ __nv_bfloat16 g_qlo[NELEM];
__device__ __nv_bfloat16 g_khi[NELEM];
__device__ __nv_bfloat16 g_klo[NELEM];
__device__ __half        g_vh [NELEM];
__device__ __half g_ah [NELEM];
__device__ __half g_wqh[NELEM];
__device__ __half g_wkh[NELEM];
__device__ __half g_wvh[NELEM];
__device__ __half g_woh[NELEM];

// ==============================================================================
// helpers
// ==============================================================================
__device__ __forceinline__ void cp16(uint32_t dst, const void* src) {
    asm volatile("cp.async.cg.shared.global [%0], [%1], 16;" :: "r"(dst), "l"(src));
}

__device__ __forceinline__ void ldsm4(uint32_t* r, uint32_t a) {
    asm volatile("ldmatrix.sync.aligned.m8n8.x4.shared.b16 {%0,%1,%2,%3}, [%4];"
                 : "=r"(r[0]), "=r"(r[1]), "=r"(r[2]), "=r"(r[3]) : "r"(a));
}

__device__ __forceinline__ void ldsm4t(uint32_t* r, uint32_t a) {
    asm volatile("ldmatrix.sync.aligned.m8n8.x4.trans.shared.b16 {%0,%1,%2,%3}, [%4];"
                 : "=r"(r[0]), "=r"(r[1]), "=r"(r[2]), "=r"(r[3]) : "r"(a));
}

__device__ __forceinline__ void mma_bf16(float* c, const uint32_t* a,
                                         uint32_t b0, uint32_t b1) {
    asm volatile(
        "mma.sync.aligned.m16n8k16.row.col.f32.bf16.bf16.f32 "
        "{%0,%1,%2,%3}, {%4,%5,%6,%7}, {%8,%9}, {%0,%1,%2,%3};"
        : "+f"(c[0]), "+f"(c[1]), "+f"(c[2]), "+f"(c[3])
        : "r"(a[0]), "r"(a[1]), "r"(a[2]), "r"(a[3]), "r"(b0), "r"(b1));
}

__device__ __forceinline__ void mma_f16(float* c, const uint32_t* a,
                                        uint32_t b0, uint32_t b1) {
    asm volatile(
        "mma.sync.aligned.m16n8k16.row.col.f32.f16.f16.f32 "
        "{%0,%1,%2,%3}, {%4,%5,%6,%7}, {%8,%9}, {%0,%1,%2,%3};"
        : "+f"(c[0]), "+f"(c[1]), "+f"(c[2]), "+f"(c[3])
        : "r"(a[0]), "r"(a[1]), "r"(a[2]), "r"(a[3]), "r"(b0), "r"(b1));
}

// ==============================================================================
// fused fp32 -> fp16 conversion: z selects tensor
// ==============================================================================
__global__ void cvt_f16_multi(const float* __restrict__ x0, __half* __restrict__ y0,
                              const float* __restrict__ x1, __half* __restrict__ y1,
                              const float* __restrict__ x2, __half* __restrict__ y2,
                              const float* __restrict__ x3, __half* __restrict__ y3,
                              const float* __restrict__ x4, __half* __restrict__ y4)
{
    const int z = blockIdx.y;
    const float* x = (z == 0) ? x0 : (z == 1) ? x1 : (z == 2) ? x2 : (z == 3) ? x3 : x4;
    __half*      y = (z == 0) ? y0 : (z == 1) ? y1 : (z == 2) ? y2 : (z == 3) ? y3 : y4;
    const int i = blockIdx.x * blockDim.x + threadIdx.x;
    float4 v = ((const float4*)x)[i];
    ((half2*)y)[2 * i]     = __floats2half2_rn(v.x, v.y);
    ((half2*)y)[2 * i + 1] = __floats2half2_rn(v.z, v.w);
}

__global__ void cvt_f16(const float* __restrict__ x, __half* __restrict__ y)
{
    const int i = blockIdx.x * blockDim.x + threadIdx.x;
    float4 v = ((const float4*)x)[i];
    ((half2*)y)[2 * i]     = __floats2half2_rn(v.x, v.y);
    ((half2*)y)[2 * i + 1] = __floats2half2_rn(v.z, v.w);
}

// ==============================================================================
// fp16 tensor-core GEMM (NT): C = A * B^T. 128x256 block, BK=64, 3-stage
// cp.async pipeline, ONE __syncthreads per k-iteration (64 iters).
// Rows padded to 144B (validated conflict-free in round 5).
// Fused QKV variant: blockIdx.z selects (B, C) pair.
// ==============================================================================
#define HSTR  144
#define SOFFB (128 * HSTR)                  // 18432
#define SSTG  (384 * HSTR)                  // 55296 per stage
#define GEMM_SMEM (3 * SSTG)                // 165888

__device__ __forceinline__ void gemm_body(const __half* __restrict__ A,
                                          const __half* __restrict__ B,
                                          float* __restrict__ C,
                                          uint32_t sb, int m0, int n0)
{
    const int tid  = threadIdx.x;
    const int lane = tid & 31;
    const int warp = tid >> 5;
    const int wm   = warp & 1;
    const int wn   = warp >> 1;

    float acc[4][8][4];
#pragma unroll
    for (int i = 0; i < 4; i++)
#pragma unroll
        for (int j = 0; j < 8; j++)
#pragma unroll
            for (int r = 0; r < 4; r++) acc[i][j][r] = 0.f;

    // loader: A 128 rows x 8 chunks, B 256 rows x 8 chunks (16B each)
    const int ldr = tid >> 3;      // 0..31 base row
    const int ldc = tid & 7;       // chunk
    auto load_stage = [&](int stage, int kt) {
        const uint32_t st = sb + stage * SSTG;
#pragma unroll
        for (int i = 0; i < 4; i++) {
            const int r = ldr + 32 * i;
            cp16(st + r * HSTR + ldc * 16,
                 A + (size_t)(m0 + r) * 4096 + kt + ldc * 8);
        }
#pragma unroll
        for (int i = 0; i < 8; i++) {
            const int r = ldr + 32 * i;
            cp16(st + SOFFB + r * HSTR + ldc * 16,
                 B + (size_t)(n0 + r) * 4096 + kt + ldc * 8);
        }
        asm volatile("cp.async.commit_group;");
    };

    load_stage(0, 0);
    load_stage(1, 64);

    const uint32_t arow = (lane & 15) * HSTR + (lane >> 4) * 16;
    const uint32_t brow = ((lane & 7) + ((lane >> 4) & 1) * 8) * HSTR
                        + ((lane >> 3) & 1) * 16;
    const int NT = 4096 / 64;   // 64

    int stage = 0;
    for (int t = 0; t < NT; t++) {
        if (t < NT - 1) asm volatile("cp.async.wait_group 1;");
        else            asm volatile("cp.async.wait_group 0;");
        __syncthreads();
        if (t + 2 < NT) {
            int ns = stage + 2; if (ns >= 3) ns -= 3;
            load_stage(ns, (t + 2) * 64);
        }

        const uint32_t ab = sb + stage * SSTG + (wm * 64) * HSTR;
        const uint32_t bb = sb + stage * SSTG + SOFFB + (wn * 64) * HSTR;

#pragma unroll
        for (int ks = 0; ks < 4; ks++) {
            const int kb = ks * 32;
            uint32_t af[4][4];
#pragma unroll
            for (int mt = 0; mt < 4; mt++)
                ldsm4(af[mt], ab + mt * 16 * HSTR + arow + kb);
#pragma unroll
            for (int np = 0; np < 4; np++) {
                uint32_t b4[4];
                ldsm4(b4, bb + np * 16 * HSTR + brow + kb);
#pragma unroll
                for (int mt = 0; mt < 4; mt++) {
                    mma_f16(acc[mt][np * 2],     af[mt], b4[0], b4[1]);
                    mma_f16(acc[mt][np * 2 + 1], af[mt], b4[2], b4[3]);
                }
            }
        }
        if (++stage == 3) stage = 0;
    }

    const int g  = lane >> 2;
    const int qd = lane & 3;
#pragma unroll
    for (int mt = 0; mt < 4; mt++) {
        const int r0 = m0 + wm * 64 + mt * 16 + g;
#pragma unroll
        for (int nt = 0; nt < 8; nt++) {
            const int col = n0 + wn * 64 + nt * 8 + qd * 2;
            *(float2*)&C[(size_t)r0 * 4096 + col] =
                make_float2(acc[mt][nt][0], acc[mt][nt][1]);
            *(float2*)&C[(size_t)(r0 + 8) * 4096 + col] =
                make_float2(acc[mt][nt][2], acc[mt][nt][3]);
        }
    }
}

__global__ __launch_bounds__(256, 1)
void gemm_f16(const __half* __restrict__ A, const __half* __restrict__ B,
              float* __restrict__ C)
{
    extern __shared__ __align__(16) char smg[];
    gemm_body(A, B, C, (uint32_t)__cvta_generic_to_shared(smg),
              blockIdx.y * 128, blockIdx.x * 256);
}

__global__ __launch_bounds__(256, 1)
void gemm_f16_qkv(const __half* __restrict__ A,
                  const __half* __restrict__ Bq, const __half* __restrict__ Bk,
                  const __half* __restrict__ Bv,
                  float* __restrict__ Cq, float* __restrict__ Ck,
                  float* __restrict__ Cv)
{
    extern __shared__ __align__(16) char smg[];
    const int z = blockIdx.z;
    const __half* B = (z == 0) ? Bq : (z == 1) ? Bk : Bv;
    float*        C = (z == 0) ? Cq : (z == 1) ? Ck : Cv;
    gemm_body(A, B, C, (uint32_t)__cvta_generic_to_shared(smg),
              blockIdx.y * 128, blockIdx.x * 256);
}

// ==============================================================================
// prep: RoPE on q,k + emit bf16 hi/lo planes (q,k) and fp16 plane (v).
// ==============================================================================
__global__ void prep_qkv(const float* __restrict__ q, const float* __restrict__ k,
                         const float* __restrict__ v,
                         __nv_bfloat16* __restrict__ qhi, __nv_bfloat16* __restrict__ qlo,
                         __nv_bfloat16* __restrict__ khi, __nv_bfloat16* __restrict__ klo,
                         __half* __restrict__ vh)
{
    const int i = blockIdx.x * blockDim.x + threadIdx.x;
    const int e = i * 4;
    const int s = e >> 12;
    const int hd = e & 255;

    float4 qv = ((const float4*)q)[i];
    float4 kv = ((const float4*)k)[i];
    float4 vv = ((const float4*)v)[i];

    if (hd < ROT) {
        const int j0 = hd >> 1;
        float a0 = (float)s * powf(10000.f, -(float)j0 / 32.f);
        float a1 = (float)s * powf(10000.f, -(float)(j0 + 1) / 32.f);
        float s0, c0, s1, c1;
        sincosf(a0, &s0, &c0);
        sincosf(a1, &s1, &c1);
        float x, y;
        x = qv.x; y = qv.y; qv.x = x * c0 - y * s0; qv.y = y * c0 + x * s0;
        x = qv.z; y = qv.w; qv.z = x * c1 - y * s1; qv.w = y * c1 + x * s1;
        x = kv.x; y = kv.y; kv.x = x * c0 - y * s0; kv.y = y * c0 + x * s0;
        x = kv.z; y = kv.w; kv.z = x * c1 - y * s1; kv.w = y * c1 + x * s1;
    }

#define SPLIT2(vx, vy, hi2, lo2) {                                         \
        __nv_bfloat16 _h0 = __float2bfloat16_rn(vx);                       \
        __nv_bfloat16 _h1 = __float2bfloat16_rn(vy);                       \
        hi2 = __nv_bfloat162(_h0, _h1);                                    \
        lo2 = __nv_bfloat162(__float2bfloat16_rn((vx) - __bfloat162float(_h0)), \
                             __float2bfloat16_rn((vy) - __bfloat162float(_h1))); }

    __nv_bfloat162 h2, l2;
    SPLIT2(qv.x, qv.y, h2, l2);
    ((__nv_bfloat162*)qhi)[2 * i]     = h2; ((__nv_bfloat162*)qlo)[2 * i]     = l2;
    SPLIT2(qv.z, qv.w, h2, l2);
    ((__nv_bfloat162*)qhi)[2 * i + 1] = h2; ((__nv_bfloat162*)qlo)[2 * i + 1] = l2;
    SPLIT2(kv.x, kv.y, h2, l2);
    ((__nv_bfloat162*)khi)[2 * i]     = h2; ((__nv_bfloat162*)klo)[2 * i]     = l2;
    SPLIT2(kv.z, kv.w, h2, l2);
    ((__nv_bfloat162*)khi)[2 * i + 1] = h2; ((__nv_bfloat162*)klo)[2 * i + 1] = l2;

    ((half2*)vh)[2 * i]     = __floats2half2_rn(vv.x, vv.y);
    ((half2*)vh)[2 * i + 1] = __floats2half2_rn(vv.z, vv.w);
#undef SPLIT2
}

// ==============================================================================
// Tensor-core causal flash attention (validated round 4/5/6; unchanged).
// ==============================================================================
#define QSTR 528
#define PSTR 144
#define S_QHI 0
#define S_QLO 33792
#define S_KHI 67584
#define S_KLO 101376
#define S_V   135168
#define S_SB  168960
#define S_P   186368
#define S_CORR 195584
#define S_LINV 195840
#define ATT_SMEM 196096

__global__ __launch_bounds__(256, 1)
void attn_mma(const __nv_bfloat16* __restrict__ Qhi, const __nv_bfloat16* __restrict__ Qlo,
              const __nv_bfloat16* __restrict__ Khi, const __nv_bfloat16* __restrict__ Klo,
              const __half* __restrict__ Vh, float* __restrict__ O)
{
    extern __shared__ __align__(16) char sm[];
    const uint32_t sb = (uint32_t)__cvta_generic_to_shared(sm);
    float* SBf    = (float*)(sm + S_SB);
    float* corr_s = (float*)(sm + S_CORR);
    float* linv_s = (float*)(sm + S_LINV);

    const int tid   = threadIdx.x;
    const int lane  = tid & 31;
    const int wid   = tid >> 5;
    const int grp   = wid >> 2;
    const int slice = (wid & 3) * 16;
    const int g     = lane >> 2;
    const int qd    = lane & 3;

    const int h    = blockIdx.y;
    const int m0   = ((int)gridDim.x - 1 - (int)blockIdx.x) * 64;
    const int cb   = h * HD;
    const int doff = grp * 128;

    for (int f = tid; f < 2048; f += 256) {
        const int r = f >> 5, c = f & 31;
        const size_t go = (size_t)(m0 + r) * EMBED + cb + c * 8;
        cp16(sb + S_QHI + r * QSTR + c * 16, Qhi + go);
        cp16(sb + S_QLO + r * QSTR + c * 16, Qlo + go);
    }

    float of[16][4];
#pragma unroll
    for (int j = 0; j < 16; j++)
#pragma unroll
        for (int r = 0; r < 4; r++) of[j][r] = 0.f;
    float mr0 = -1e30f, mr1 = -1e30f, l0 = 0.f, l1 = 0.f;

    const int ntl = m0 / 64 + 1;
    for (int t = 0; t < ntl; t++) {
        const int n0 = t * 64;
        __syncthreads();

        for (int f = tid; f < 2048; f += 256) {
            const int r = f >> 5, c = f & 31;
            const size_t go = (size_t)(n0 + r) * EMBED + cb + c * 8;
            cp16(sb + S_KHI + r * QSTR + c * 16, Khi + go);
            cp16(sb + S_KLO + r * QSTR + c * 16, Klo + go);
            cp16(sb + S_V   + r * QSTR + c * 16, Vh  + go);
        }
        asm volatile("cp.async.commit_group;");
        asm volatile("cp.async.wait_group 0;");
        __syncthreads();

        float sf[8][4];
#pragma unroll
        for (int nt = 0; nt < 8; nt++)
#pragma unroll
            for (int r = 0; r < 4; r++) sf[nt][r] = 0.f;

        const uint32_t qa = sb + S_QHI + (slice + (lane & 15)) * QSTR + (lane >> 4) * 16;
#pragma unroll
        for (int kc = 0; kc < 8; kc++) {
            const int dby = (doff + kc * 16) * 2;
            uint32_t qh[4], ql[4];
            ldsm4(qh, qa + dby);
            ldsm4(ql, qa + dby + (S_QLO - S_QHI));
#pragma unroll
            for (int kg = 0; kg < 4; kg++) {
                const int key = kg * 16 + (lane & 7) + ((lane >> 4) & 1) * 8;
                const uint32_t ba = sb + S_KHI + key * QSTR + dby + ((lane >> 3) & 1) * 16;
                uint32_t kh[4], kl[4];
                ldsm4(kh, ba);
                ldsm4(kl, ba + (S_KLO - S_KHI));
                mma_bf16(sf[2 * kg],     qh, kh[0], kh[1]);
                mma_bf16(sf[2 * kg],     qh, kl[0], kl[1]);
                mma_bf16(sf[2 * kg],     ql, kh[0], kh[1]);
                mma_bf16(sf[2 * kg + 1], qh, kh[2], kh[3]);
                mma_bf16(sf[2 * kg + 1], qh, kl[2], kl[3]);
                mma_bf16(sf[2 * kg + 1], ql, kh[2], kh[3]);
            }
        }

        if (grp == 1) {
#pragma unroll
            for (int nt = 0; nt < 8; nt++) {
                const int col = nt * 8 + qd * 2;
                *(float2*)&SBf[(slice + g) * 68 + col]     = make_float2(sf[nt][0], sf[nt][1]);
                *(float2*)&SBf[(slice + g + 8) * 68 + col] = make_float2(sf[nt][2], sf[nt][3]);
            }
        }
        __syncthreads();

        if (grp == 0) {
            const int row0 = m0 + slice + g, row1 = row0 + 8;
            float px0 = -1e30f, px1 = -1e30f;
#pragma unroll
            for (int nt = 0; nt < 8; nt++) {
                const int col = nt * 8 + qd * 2;
                const float2 b0 = *(float2*)&SBf[(slice + g) * 68 + col];
                const float2 b1 = *(float2*)&SBf[(slice + g + 8) * 68 + col];
                const int cg = n0 + col;
                sf[nt][0] = (cg     <= row0) ? (sf[nt][0] + b0.x) * 0.0625f : -1e30f;
                sf[nt][1] = (cg + 1 <= row0) ? (sf[nt][1] + b0.y) * 0.0625f : -1e30f;
                sf[nt][2] = (cg     <= row1) ? (sf[nt][2] + b1.x) * 0.0625f : -1e30f;
                sf[nt][3] = (cg + 1 <= row1) ? (sf[nt][3] + b1.y) * 0.0625f : -1e30f;
                px0 = fmaxf(px0, fmaxf(sf[nt][0], sf[nt][1]));
                px1 = fmaxf(px1, fmaxf(sf[nt][2], sf[nt][3]));
            }
            px0 = fmaxf(px0, __shfl_xor_sync(0xffffffffu, px0, 1));
            px0 = fmaxf(px0, __shfl_xor_sync(0xffffffffu, px0, 2));
            px1 = fmaxf(px1, __shfl_xor_sync(0xffffffffu, px1, 1));
            px1 = fmaxf(px1, __shfl_xor_sync(0xffffffffu, px1, 2));
            const float mn0 = fmaxf(mr0, px0), mn1 = fmaxf(mr1, px1);
            const float cr0 = __expf(mr0 - mn0), cr1 = __expf(mr1 - mn1);
            mr0 = mn0; mr1 = mn1;
            float s0 = 0.f, s1 = 0.f;
#pragma unroll
            for (int nt = 0; nt < 8; nt++) {
                const float p0 = __expf(sf[nt][0] - mn0);
                const float p1 = __expf(sf[nt][1] - mn0);
                const float p2 = __expf(sf[nt][2] - mn1);
                const float p3 = __expf(sf[nt][3] - mn1);
                s0 += p0 + p1; s1 += p2 + p3;
                const int col = nt * 8 + qd * 2;
                *(half2*)(sm + S_P + (slice + g) * PSTR + col * 2)     = __floats2half2_rn(p0, p1);
                *(half2*)(sm + S_P + (slice + g + 8) * PSTR + col * 2) = __floats2half2_rn(p2, p3);
            }
            s0 += __shfl_xor_sync(0xffffffffu, s0, 1);
            s0 += __shfl_xor_sync(0xffffffffu, s0, 2);
            s1 += __shfl_xor_sync(0xffffffffu, s1, 1);
            s1 += __shfl_xor_sync(0xffffffffu, s1, 2);
            l0 = l0 * cr0 + s0;
            l1 = l1 * cr1 + s1;
            if (qd == 0) { corr_s[slice + g] = cr0; corr_s[slice + g + 8] = cr1; }
        }
        __syncthreads();

        {
            const float c0 = corr_s[slice + g], c1 = corr_s[slice + g + 8];
#pragma unroll
            for (int j = 0; j < 16; j++) {
                of[j][0] *= c0; of[j][1] *= c0; of[j][2] *= c1; of[j][3] *= c1;
            }
        }
#pragma unroll
        for (int kc = 0; kc < 4; kc++) {
            uint32_t pa[4];
            ldsm4(pa, sb + S_P + (slice + (lane & 15)) * PSTR + kc * 32 + (lane >> 4) * 16);
            const int key = kc * 16 + (lane & 7) + ((lane >> 3) & 1) * 8;
#pragma unroll
            for (int jj = 0; jj < 8; jj++) {
                uint32_t vb[4];
                ldsm4t(vb, sb + S_V + key * QSTR + (doff + jj * 16) * 2 + ((lane >> 4) & 1) * 16);
                mma_f16(of[2 * jj],     pa, vb[0], vb[1]);
                mma_f16(of[2 * jj + 1], pa, vb[2], vb[3]);
            }
        }
    }

    if (grp == 0 && qd == 0) {
        linv_s[slice + g]     = 1.f / l0;
        linv_s[slice + g + 8] = 1.f / l1;
    }
    __syncthreads();
    const float ia = linv_s[slice + g], ib = linv_s[slice + g + 8];
    const int row0 = m0 + slice + g;
#pragma unroll
    for (int nt = 0; nt < 16; nt++) {
        const int col = cb + doff + nt * 8 + qd * 2;
        *(float2*)&O[(size_t)row0 * EMBED + col] =
            make_float2(of[nt][0] * ia, of[nt][1] * ia);
        *(float2*)&O[(size_t)(row0 + 8) * EMBED + col] =
            make_float2(of[nt][2] * ib, of[nt][3] * ib);
    }
}

// ==============================================================================
// launch
// ==============================================================================
extern "C" void kernel_launch(void* const* d_in, const int* in_sizes, int n_in,
                              void* d_out, int out_size)
{
    (void)in_sizes; (void)n_in; (void)out_size;
    const float* X  = (const float*)d_in[0];
    const float* Wq = (const float*)d_in[1];
    const float* Wk = (const float*)d_in[2];
    const float* Wv = (const float*)d_in[3];
    const float* Wo = (const float*)d_in[4];
    float* out = (float*)d_out;

    float *q, *k, *v, *ao;
    __nv_bfloat16 *qhi, *qlo, *khi, *klo;
    __half *vh, *ah, *wqh, *wkh, *wvh, *woh;
    cudaGetSymbolAddress((void**)&q,   g_q);
    cudaGetSymbolAddress((void**)&k,   g_k);
    cudaGetSymbolAddress((void**)&v,   g_v);
    cudaGetSymbolAddress((void**)&ao,  g_ao);
    cudaGetSymbolAddress((void**)&qhi, g_qhi);
    cudaGetSymbolAddress((void**)&qlo, g_qlo);
    cudaGetSymbolAddress((void**)&khi, g_khi);
    cudaGetSymbolAddress((void**)&klo, g_klo);
    cudaGetSymbolAddress((void**)&vh,  g_vh);
    cudaGetSymbolAddress((void**)&ah,  g_ah);
    cudaGetSymbolAddress((void**)&wqh, g_wqh);
    cudaGetSymbolAddress((void**)&wkh, g_wkh);
    cudaGetSymbolAddress((void**)&wvh, g_wvh);
    cudaGetSymbolAddress((void**)&woh, g_woh);

    cudaFuncSetAttribute(gemm_f16,
                         cudaFuncAttributeMaxDynamicSharedMemorySize, GEMM_SMEM);
    cudaFuncSetAttribute(gemm_f16_qkv,
                         cudaFuncAttributeMaxDynamicSharedMemorySize, GEMM_SMEM);
    cudaFuncSetAttribute(attn_mma,
                         cudaFuncAttributeMaxDynamicSharedMemorySize, ATT_SMEM);

    const int CVB = NELEM / 4 / 256;
    dim3 gc(CVB, 5);
    cvt_f16_multi<<<gc, 256>>>(X, ah, Wq, wqh, Wk, wkh, Wv, wvh, Wo, woh);

    dim3 gq(4096 / 256, 4096 / 128, 3);    // fused QKV
    gemm_f16_qkv<<<gq, 256, GEMM_SMEM>>>(ah, wqh, wkh, wvh, q, k, v);

    prep_qkv<<<NELEM / 4 / 256, 256>>>(q, k, v, qhi, qlo, khi, klo, vh);

    dim3 ga(SEQ / 64, HEADS);
    attn_mma<<<ga, 256, ATT_SMEM>>>(qhi, qlo, khi, klo, vh, ao);

    cvt_f16<<<CVB, 256>>>(ao, ah);
    dim3 gg(4096 / 256, 4096 / 128);
    gemm_f16<<<gg, 256, GEMM_SMEM>>>(ah, woh, out);
}

// round 8
// speedup vs baseline: 5.2332x; 1.0216x over previous
#include <cuda_runtime.h>
#include <cuda_bf16.h>
#include <cuda_fp16.h>
#include <math.h>
#include <stdint.h>

#define SEQ   4096
#define EMBED 4096
#define HEADS 16
#define HD    256
#define ROT   64
#define NELEM (SEQ * EMBED)

// ---------------- scratch (allocation-free rule: __device__ globals) ----------
__device__ __nv_bfloat16 g_qhi[NELEM];
__device__ __nv_bfloat16 g_qlo[NELEM];
__device__ __nv_bfloat16 g_khi[NELEM];
__device__ __nv_bfloat16 g_klo[NELEM];
__device__ __half        g_vh [NELEM];
__device__ __half g_ah [NELEM];     // fp16 activations (X, later attn out)
__device__ __half g_wqh[NELEM];
__device__ __half g_wkh[NELEM];
__device__ __half g_wvh[NELEM];
__device__ __half g_woh[NELEM];

// ==============================================================================
// helpers
// ==============================================================================
__device__ __forceinline__ void cp16(uint32_t dst, const void* src) {
    asm volatile("cp.async.cg.shared.global [%0], [%1], 16;" :: "r"(dst), "l"(src));
}

__device__ __forceinline__ void ldsm4(uint32_t* r, uint32_t a) {
    asm volatile("ldmatrix.sync.aligned.m8n8.x4.shared.b16 {%0,%1,%2,%3}, [%4];"
                 : "=r"(r[0]), "=r"(r[1]), "=r"(r[2]), "=r"(r[3]) : "r"(a));
}

__device__ __forceinline__ void ldsm4t(uint32_t* r, uint32_t a) {
    asm volatile("ldmatrix.sync.aligned.m8n8.x4.trans.shared.b16 {%0,%1,%2,%3}, [%4];"
                 : "=r"(r[0]), "=r"(r[1]), "=r"(r[2]), "=r"(r[3]) : "r"(a));
}

__device__ __forceinline__ void mma_bf16(float* c, const uint32_t* a,
                                         uint32_t b0, uint32_t b1) {
    asm volatile(
        "mma.sync.aligned.m16n8k16.row.col.f32.bf16.bf16.f32 "
        "{%0,%1,%2,%3}, {%4,%5,%6,%7}, {%8,%9}, {%0,%1,%2,%3};"
        : "+f"(c[0]), "+f"(c[1]), "+f"(c[2]), "+f"(c[3])
        : "r"(a[0]), "r"(a[1]), "r"(a[2]), "r"(a[3]), "r"(b0), "r"(b1));
}

__device__ __forceinline__ void mma_f16(float* c, const uint32_t* a,
                                        uint32_t b0, uint32_t b1) {
    asm volatile(
        "mma.sync.aligned.m16n8k16.row.col.f32.f16.f16.f32 "
        "{%0,%1,%2,%3}, {%4,%5,%6,%7}, {%8,%9}, {%0,%1,%2,%3};"
        : "+f"(c[0]), "+f"(c[1]), "+f"(c[2]), "+f"(c[3])
        : "r"(a[0]), "r"(a[1]), "r"(a[2]), "r"(a[3]), "r"(b0), "r"(b1));
}

// ==============================================================================
// fused fp32 -> fp16 conversion: y-dim selects tensor (X + 4 weights)
// ==============================================================================
__global__ void cvt_f16_multi(const float* __restrict__ x0, __half* __restrict__ y0,
                              const float* __restrict__ x1, __half* __restrict__ y1,
                              const float* __restrict__ x2, __half* __restrict__ y2,
                              const float* __restrict__ x3, __half* __restrict__ y3,
                              const float* __restrict__ x4, __half* __restrict__ y4)
{
    const int z = blockIdx.y;
    const float* x = (z == 0) ? x0 : (z == 1) ? x1 : (z == 2) ? x2 : (z == 3) ? x3 : x4;
    __half*      y = (z == 0) ? y0 : (z == 1) ? y1 : (z == 2) ? y2 : (z == 3) ? y3 : y4;
    const int i = blockIdx.x * blockDim.x + threadIdx.x;
    float4 v = ((const float4*)x)[i];
    ((half2*)y)[2 * i]     = __floats2half2_rn(v.x, v.y);
    ((half2*)y)[2 * i + 1] = __floats2half2_rn(v.z, v.w);
}

// ==============================================================================
// RoPE + bf16 hi/lo plane split on an fp32 column pair (col even).
// ==============================================================================
__device__ __forceinline__ void rope_split_store(float c0, float c1, int row, int col,
                                                 __nv_bfloat16* hi, __nv_bfloat16* lo)
{
    const int hd = col & 255;
    if (hd < ROT) {
        const float inv = powf(10000.f, -(float)(hd >> 1) / 32.f);
        float sn, cs;
        sincosf((float)row * inv, &sn, &cs);
        const float x = c0, y = c1;
        c0 = x * cs - y * sn;
        c1 = y * cs + x * sn;
    }
    const __nv_bfloat16 h0 = __float2bfloat16_rn(c0);
    const __nv_bfloat16 h1 = __float2bfloat16_rn(c1);
    const size_t idx = ((size_t)row * EMBED + col) >> 1;
    ((__nv_bfloat162*)hi)[idx] = __nv_bfloat162(h0, h1);
    ((__nv_bfloat162*)lo)[idx] =
        __nv_bfloat162(__float2bfloat16_rn(c0 - __bfloat162float(h0)),
                       __float2bfloat16_rn(c1 - __bfloat162float(h1)));
}

// ==============================================================================
// fp16 tensor-core GEMM (NT): C = A * B^T. 128x256 block, BK=64, 3-stage
// cp.async pipeline, ONE __syncthreads per k-iteration, 16 warps (512 thr),
// warp tile 32x64. Rows padded to 144B (conflict-free, validated round 5).
// ==============================================================================
#define HSTR  144
#define SOFFB (128 * HSTR)                  // 18432
#define SSTG  (384 * HSTR)                  // 55296 per stage
#define GEMM_SMEM (3 * SSTG)                // 165888
#define GTHR  512

// mode: 0 = plain fp32 store, 1 = rope+split bf16 planes, 2 = fp16 store
struct EpiTargets {
    float* c;
    __nv_bfloat16* hi;
    __nv_bfloat16* lo;
    __half* h;
};

__device__ __forceinline__ void gemm_body(const __half* __restrict__ A,
                                          const __half* __restrict__ B,
                                          uint32_t sb, int m0, int n0,
                                          int mode, EpiTargets tg)
{
    const int tid  = threadIdx.x;
    const int lane = tid & 31;
    const int warp = tid >> 5;
    const int wm   = warp & 3;              // 32-row slab
    const int wn   = warp >> 2;             // 64-col slab

    float acc[2][8][4];
#pragma unroll
    for (int i = 0; i < 2; i++)
#pragma unroll
        for (int j = 0; j < 8; j++)
#pragma unroll
            for (int r = 0; r < 4; r++) acc[i][j][r] = 0.f;

    const int ldr = tid >> 3;      // 0..63 base row
    const int ldc = tid & 7;       // chunk
    auto load_stage = [&](int stage, int kt) {
        const uint32_t st = sb + stage * SSTG;
#pragma unroll
        for (int i = 0; i < 2; i++) {
            const int r = ldr + 64 * i;
            cp16(st + r * HSTR + ldc * 16,
                 A + (size_t)(m0 + r) * 4096 + kt + ldc * 8);
        }
#pragma unroll
        for (int i = 0; i < 4; i++) {
            const int r = ldr + 64 * i;
            cp16(st + SOFFB + r * HSTR + ldc * 16,
                 B + (size_t)(n0 + r) * 4096 + kt + ldc * 8);
        }
        asm volatile("cp.async.commit_group;");
    };

    load_stage(0, 0);
    load_stage(1, 64);

    const uint32_t arow = (lane & 15) * HSTR + (lane >> 4) * 16;
    const uint32_t brow = ((lane & 7) + ((lane >> 4) & 1) * 8) * HSTR
                        + ((lane >> 3) & 1) * 16;
    const int NT = 4096 / 64;   // 64

    int stage = 0;
    for (int t = 0; t < NT; t++) {
        if (t < NT - 1) asm volatile("cp.async.wait_group 1;");
        else            asm volatile("cp.async.wait_group 0;");
        __syncthreads();
        if (t + 2 < NT) {
            int ns = stage + 2; if (ns >= 3) ns -= 3;
            load_stage(ns, (t + 2) * 64);
        }

        const uint32_t ab = sb + stage * SSTG + (wm * 32) * HSTR;
        const uint32_t bb = sb + stage * SSTG + SOFFB + (wn * 64) * HSTR;

#pragma unroll
        for (int ks = 0; ks < 4; ks++) {
            const int kb = ks * 32;
            uint32_t af[2][4];
#pragma unroll
            for (int mt = 0; mt < 2; mt++)
                ldsm4(af[mt], ab + mt * 16 * HSTR + arow + kb);
#pragma unroll
            for (int np = 0; np < 4; np++) {
                uint32_t b4[4];
                ldsm4(b4, bb + np * 16 * HSTR + brow + kb);
#pragma unroll
                for (int mt = 0; mt < 2; mt++) {
                    mma_f16(acc[mt][np * 2],     af[mt], b4[0], b4[1]);
                    mma_f16(acc[mt][np * 2 + 1], af[mt], b4[2], b4[3]);
                }
            }
        }
        if (++stage == 3) stage = 0;
    }

    const int g  = lane >> 2;
    const int qd = lane & 3;
#pragma unroll
    for (int mt = 0; mt < 2; mt++) {
        const int r0 = m0 + wm * 32 + mt * 16 + g;
#pragma unroll
        for (int nt = 0; nt < 8; nt++) {
            const int col = n0 + wn * 64 + nt * 8 + qd * 2;
            if (mode == 0) {
                *(float2*)&tg.c[(size_t)r0 * 4096 + col] =
                    make_float2(acc[mt][nt][0], acc[mt][nt][1]);
                *(float2*)&tg.c[(size_t)(r0 + 8) * 4096 + col] =
                    make_float2(acc[mt][nt][2], acc[mt][nt][3]);
            } else if (mode == 1) {
                rope_split_store(acc[mt][nt][0], acc[mt][nt][1], r0,     col, tg.hi, tg.lo);
                rope_split_store(acc[mt][nt][2], acc[mt][nt][3], r0 + 8, col, tg.hi, tg.lo);
            } else {
                ((half2*)tg.h)[((size_t)r0 * 4096 + col) >> 1] =
                    __floats2half2_rn(acc[mt][nt][0], acc[mt][nt][1]);
                ((half2*)tg.h)[((size_t)(r0 + 8) * 4096 + col) >> 1] =
                    __floats2half2_rn(acc[mt][nt][2], acc[mt][nt][3]);
            }
        }
    }
}

__global__ __launch_bounds__(GTHR, 1)
void gemm_f16_out(const __half* __restrict__ A, const __half* __restrict__ B,
                  float* __restrict__ C)
{
    extern __shared__ __align__(16) char smg[];
    EpiTargets tg; tg.c = C; tg.hi = nullptr; tg.lo = nullptr; tg.h = nullptr;
    gemm_body(A, B, (uint32_t)__cvta_generic_to_shared(smg),
              blockIdx.y * 128, blockIdx.x * 256, 0, tg);
}

__global__ __launch_bounds__(GTHR, 1)
void gemm_f16_qkv(const __half* __restrict__ A,
                  const __half* __restrict__ Bq, const __half* __restrict__ Bk,
                  const __half* __restrict__ Bv,
                  __nv_bfloat16* __restrict__ qhi, __nv_bfloat16* __restrict__ qlo,
                  __nv_bfloat16* __restrict__ khi, __nv_bfloat16* __restrict__ klo,
                  __half* __restrict__ vh)
{
    extern __shared__ __align__(16) char smg[];
    const int z = blockIdx.z;
    const __half* B = (z == 0) ? Bq : (z == 1) ? Bk : Bv;
    EpiTargets tg;
    tg.c = nullptr;
    tg.hi = (z == 0) ? qhi : khi;
    tg.lo = (z == 0) ? qlo : klo;
    tg.h  = vh;
    gemm_body(A, B, (uint32_t)__cvta_generic_to_shared(smg),
              blockIdx.y * 128, blockIdx.x * 256, (z == 2) ? 2 : 1, tg);
}

// ==============================================================================
// Tensor-core causal flash attention (core validated rounds 4-7).
// Output now written as fp16 directly into the activation buffer.
// ==============================================================================
#define QSTR 528
#define PSTR 144
#define S_QHI 0
#define S_QLO 33792
#define S_KHI 67584
#define S_KLO 101376
#define S_V   135168
#define S_SB  168960
#define S_P   186368
#define S_CORR 195584
#define S_LINV 195840
#define ATT_SMEM 196096

__global__ __launch_bounds__(256, 1)
void attn_mma(const __nv_bfloat16* __restrict__ Qhi, const __nv_bfloat16* __restrict__ Qlo,
              const __nv_bfloat16* __restrict__ Khi, const __nv_bfloat16* __restrict__ Klo,
              const __half* __restrict__ Vh, __half* __restrict__ Oh)
{
    extern __shared__ __align__(16) char sm[];
    const uint32_t sb = (uint32_t)__cvta_generic_to_shared(sm);
    float* SBf    = (float*)(sm + S_SB);
    float* corr_s = (float*)(sm + S_CORR);
    float* linv_s = (float*)(sm + S_LINV);

    const int tid   = threadIdx.x;
    const int lane  = tid & 31;
    const int wid   = tid >> 5;
    const int grp   = wid >> 2;
    const int slice = (wid & 3) * 16;
    const int g     = lane >> 2;
    const int qd    = lane & 3;

    const int h    = blockIdx.y;
    const int m0   = ((int)gridDim.x - 1 - (int)blockIdx.x) * 64;
    const int cb   = h * HD;
    const int doff = grp * 128;

    for (int f = tid; f < 2048; f += 256) {
        const int r = f >> 5, c = f & 31;
        const size_t go = (size_t)(m0 + r) * EMBED + cb + c * 8;
        cp16(sb + S_QHI + r * QSTR + c * 16, Qhi + go);
        cp16(sb + S_QLO + r * QSTR + c * 16, Qlo + go);
    }

    float of[16][4];
#pragma unroll
    for (int j = 0; j < 16; j++)
#pragma unroll
        for (int r = 0; r < 4; r++) of[j][r] = 0.f;
    float mr0 = -1e30f, mr1 = -1e30f, l0 = 0.f, l1 = 0.f;

    const int ntl = m0 / 64 + 1;
    for (int t = 0; t < ntl; t++) {
        const int n0 = t * 64;
        __syncthreads();

        for (int f = tid; f < 2048; f += 256) {
            const int r = f >> 5, c = f & 31;
            const size_t go = (size_t)(n0 + r) * EMBED + cb + c * 8;
            cp16(sb + S_KHI + r * QSTR + c * 16, Khi + go);
            cp16(sb + S_KLO + r * QSTR + c * 16, Klo + go);
            cp16(sb + S_V   + r * QSTR + c * 16, Vh  + go);
        }
        asm volatile("cp.async.commit_group;");
        asm volatile("cp.async.wait_group 0;");
        __syncthreads();

        float sf[8][4];
#pragma unroll
        for (int nt = 0; nt < 8; nt++)
#pragma unroll
            for (int r = 0; r < 4; r++) sf[nt][r] = 0.f;

        const uint32_t qa = sb + S_QHI + (slice + (lane & 15)) * QSTR + (lane >> 4) * 16;
#pragma unroll
        for (int kc = 0; kc < 8; kc++) {
            const int dby = (doff + kc * 16) * 2;
            uint32_t qh[4], ql[4];
            ldsm4(qh, qa + dby);
            ldsm4(ql, qa + dby + (S_QLO - S_QHI));
#pragma unroll
            for (int kg = 0; kg < 4; kg++) {
                const int key = kg * 16 + (lane & 7) + ((lane >> 4) & 1) * 8;
                const uint32_t ba = sb + S_KHI + key * QSTR + dby + ((lane >> 3) & 1) * 16;
                uint32_t kh[4], kl[4];
                ldsm4(kh, ba);
                ldsm4(kl, ba + (S_KLO - S_KHI));
                mma_bf16(sf[2 * kg],     qh, kh[0], kh[1]);
                mma_bf16(sf[2 * kg],     qh, kl[0], kl[1]);
                mma_bf16(sf[2 * kg],     ql, kh[0], kh[1]);
                mma_bf16(sf[2 * kg + 1], qh, kh[2], kh[3]);
                mma_bf16(sf[2 * kg + 1], qh, kl[2], kl[3]);
                mma_bf16(sf[2 * kg + 1], ql, kh[2], kh[3]);
            }
        }

        if (grp == 1) {
#pragma unroll
            for (int nt = 0; nt < 8; nt++) {
                const int col = nt * 8 + qd * 2;
                *(float2*)&SBf[(slice + g) * 68 + col]     = make_float2(sf[nt][0], sf[nt][1]);
                *(float2*)&SBf[(slice + g + 8) * 68 + col] = make_float2(sf[nt][2], sf[nt][3]);
            }
        }
        __syncthreads();

        if (grp == 0) {
            const int row0 = m0 + slice + g, row1 = row0 + 8;
            float px0 = -1e30f, px1 = -1e30f;
#pragma unroll
            for (int nt = 0; nt < 8; nt++) {
                const int col = nt * 8 + qd * 2;
                const float2 b0 = *(float2*)&SBf[(slice + g) * 68 + col];
                const float2 b1 = *(float2*)&SBf[(slice + g + 8) * 68 + col];
                const int cg = n0 + col;
                sf[nt][0] = (cg     <= row0) ? (sf[nt][0] + b0.x) * 0.0625f : -1e30f;
                sf[nt][1] = (cg + 1 <= row0) ? (sf[nt][1] + b0.y) * 0.0625f : -1e30f;
                sf[nt][2] = (cg     <= row1) ? (sf[nt][2] + b1.x) * 0.0625f : -1e30f;
                sf[nt][3] = (cg + 1 <= row1) ? (sf[nt][3] + b1.y) * 0.0625f : -1e30f;
                px0 = fmaxf(px0, fmaxf(sf[nt][0], sf[nt][1]));
                px1 = fmaxf(px1, fmaxf(sf[nt][2], sf[nt][3]));
            }
            px0 = fmaxf(px0, __shfl_xor_sync(0xffffffffu, px0, 1));
            px0 = fmaxf(px0, __shfl_xor_sync(0xffffffffu, px0, 2));
            px1 = fmaxf(px1, __shfl_xor_sync(0xffffffffu, px1, 1));
            px1 = fmaxf(px1, __shfl_xor_sync(0xffffffffu, px1, 2));
            const float mn0 = fmaxf(mr0, px0), mn1 = fmaxf(mr1, px1);
            const float cr0 = __expf(mr0 - mn0), cr1 = __expf(mr1 - mn1);
            mr0 = mn0; mr1 = mn1;
            float s0 = 0.f, s1 = 0.f;
#pragma unroll
            for (int nt = 0; nt < 8; nt++) {
                const float p0 = __expf(sf[nt][0] - mn0);
                const float p1 = __expf(sf[nt][1] - mn0);
                const float p2 = __expf(sf[nt][2] - mn1);
                const float p3 = __expf(sf[nt][3] - mn1);
                s0 += p0 + p1; s1 += p2 + p3;
                const int col = nt * 8 + qd * 2;
                *(half2*)(sm + S_P + (slice + g) * PSTR + col * 2)     = __floats2half2_rn(p0, p1);
                *(half2*)(sm + S_P + (slice + g + 8) * PSTR + col * 2) = __floats2half2_rn(p2, p3);
            }
            s0 += __shfl_xor_sync(0xffffffffu, s0, 1);
            s0 += __shfl_xor_sync(0xffffffffu, s0, 2);
            s1 += __shfl_xor_sync(0xffffffffu, s1, 1);
            s1 += __shfl_xor_sync(0xffffffffu, s1, 2);
            l0 = l0 * cr0 + s0;
            l1 = l1 * cr1 + s1;
            if (qd == 0) { corr_s[slice + g] = cr0; corr_s[slice + g + 8] = cr1; }
        }
        __syncthreads();

        {
            const float c0 = corr_s[slice + g], c1 = corr_s[slice + g + 8];
#pragma unroll
            for (int j = 0; j < 16; j++) {
                of[j][0] *= c0; of[j][1] *= c0; of[j][2] *= c1; of[j][3] *= c1;
            }
        }
#pragma unroll
        for (int kc = 0; kc < 4; kc++) {
            uint32_t pa[4];
            ldsm4(pa, sb + S_P + (slice + (lane & 15)) * PSTR + kc * 32 + (lane >> 4) * 16);
            const int key = kc * 16 + (lane & 7) + ((lane >> 3) & 1) * 8;
#pragma unroll
            for (int jj = 0; jj < 8; jj++) {
                uint32_t vb[4];
                ldsm4t(vb, sb + S_V + key * QSTR + (doff + jj * 16) * 2 + ((lane >> 4) & 1) * 16);
                mma_f16(of[2 * jj],     pa, vb[0], vb[1]);
                mma_f16(of[2 * jj + 1], pa, vb[2], vb[3]);
            }
        }
    }

    if (grp == 0 && qd == 0) {
        linv_s[slice + g]     = 1.f / l0;
        linv_s[slice + g + 8] = 1.f / l1;
    }
    __syncthreads();
    const float ia = linv_s[slice + g], ib = linv_s[slice + g + 8];
    const int row0 = m0 + slice + g;
#pragma unroll
    for (int nt = 0; nt < 16; nt++) {
        const int col = cb + doff + nt * 8 + qd * 2;
        ((half2*)Oh)[((size_t)row0 * EMBED + col) >> 1] =
            __floats2half2_rn(of[nt][0] * ia, of[nt][1] * ia);
        ((half2*)Oh)[((size_t)(row0 + 8) * EMBED + col) >> 1] =
            __floats2half2_rn(of[nt][2] * ib, of[nt][3] * ib);
    }
}

// ==============================================================================
// launch
// ==============================================================================
extern "C" void kernel_launch(void* const* d_in, const int* in_sizes, int n_in,
                              void* d_out, int out_size)
{
    (void)in_sizes; (void)n_in; (void)out_size;
    const float* X  = (const float*)d_in[0];
    const float* Wq = (const float*)d_in[1];
    const float* Wk = (const float*)d_in[2];
    const float* Wv = (const float*)d_in[3];
    const float* Wo = (const float*)d_in[4];
    float* out = (float*)d_out;

    __nv_bfloat16 *qhi, *qlo, *khi, *klo;
    __half *vh, *ah, *wqh, *wkh, *wvh, *woh;
    cudaGetSymbolAddress((void**)&qhi, g_qhi);
    cudaGetSymbolAddress((void**)&qlo, g_qlo);
    cudaGetSymbolAddress((void**)&khi, g_khi);
    cudaGetSymbolAddress((void**)&klo, g_klo);
    cudaGetSymbolAddress((void**)&vh,  g_vh);
    cudaGetSymbolAddress((void**)&ah,  g_ah);
    cudaGetSymbolAddress((void**)&wqh, g_wqh);
    cudaGetSymbolAddress((void**)&wkh, g_wkh);
    cudaGetSymbolAddress((void**)&wvh, g_wvh);
    cudaGetSymbolAddress((void**)&woh, g_woh);

    cudaFuncSetAttribute(gemm_f16_out,
                         cudaFuncAttributeMaxDynamicSharedMemorySize, GEMM_SMEM);
    cudaFuncSetAttribute(gemm_f16_qkv,
                         cudaFuncAttributeMaxDynamicSharedMemorySize, GEMM_SMEM);
    cudaFuncSetAttribute(attn_mma,
                         cudaFuncAttributeMaxDynamicSharedMemorySize, ATT_SMEM);

    const int CVB = NELEM / 4 / 256;
    dim3 gc(CVB, 5);
    cvt_f16_multi<<<gc, 256>>>(X, ah, Wq, wqh, Wk, wkh, Wv, wvh, Wo, woh);

    dim3 gq(4096 / 256, 4096 / 128, 3);    // fused QKV + rope/split epilogue
    gemm_f16_qkv<<<gq, GTHR, GEMM_SMEM>>>(ah, wqh, wkh, wvh,
                                          qhi, qlo, khi, klo, vh);

    dim3 ga(SEQ / 64, HEADS);
    attn_mma<<<ga, 256, ATT_SMEM>>>(qhi, qlo, khi, klo, vh, ah);

    dim3 gg(4096 / 256, 4096 / 128);
    gemm_f16_out<<<gg, GTHR, GEMM_SMEM>>>(ah, woh, out);
}